// round 8
// baseline (speedup 1.0000x reference)
#include <cuda_runtime.h>
#include <cuda_bf16.h>
#include <math.h>
#include <stdint.h>

// B=64, T=12, N=512, H=64, TD=32, ED=16, CHEB_K=3, D_HEADS=8, M=768
constexpr size_t NF = (size_t)768*512*64;

// ---------------- device scratch ----------------
__device__ float g_Af[512*512];
__device__ __nv_bfloat16 g_Ah[512*512], g_Al[512*512];
__device__ __nv_bfloat16 g_M2h[512*512], g_M2l[512*512];
__device__ float g_de[NF], g_yz[NF], g_hc[NF], g_rg[NF];
__device__ __nv_bfloat16 g_deh[NF], g_del[NF], g_y1h[NF], g_y1l[NF];
__device__ __nv_bfloat16 g_y2h[NF], g_y2l[NF], g_yzh[NF], g_yzl[NF];
__device__ __nv_bfloat16 g_W1h[(size_t)768*3*64*128], g_W1l[(size_t)768*3*64*128];
__device__ __nv_bfloat16 g_Wuh[(size_t)768*3*64*64],  g_Wul[(size_t)768*3*64*64];
__device__ float g_b1[768*128], g_bu[768*64];

// ---------------- ptx helpers (sm_80+ baseline only) ----------------
__device__ __forceinline__ uint32_t s2u(const void* p){
  uint32_t a;
  asm("{ .reg .u64 t; cvta.to.shared.u64 t, %1; cvt.u32.u64 %0, t; }" : "=r"(a) : "l"(p));
  return a;
}
__device__ __forceinline__ void cp16(uint32_t dst, const void* src){
  asm volatile("cp.async.cg.shared.global [%0], [%1], 16;" :: "r"(dst), "l"(src) : "memory");
}
__device__ __forceinline__ void ldm_x4(uint32_t* r, uint32_t addr){
  asm volatile("ldmatrix.sync.aligned.m8n8.x4.shared.b16 {%0,%1,%2,%3}, [%4];"
    : "=r"(r[0]), "=r"(r[1]), "=r"(r[2]), "=r"(r[3]) : "r"(addr));
}
__device__ __forceinline__ void ldm_x4t(uint32_t* r, uint32_t addr){
  asm volatile("ldmatrix.sync.aligned.m8n8.x4.trans.shared.b16 {%0,%1,%2,%3}, [%4];"
    : "=r"(r[0]), "=r"(r[1]), "=r"(r[2]), "=r"(r[3]) : "r"(addr));
}
__device__ __forceinline__ void mma_bf16(float* c, const uint32_t* a, uint32_t b0, uint32_t b1){
  asm volatile(
    "mma.sync.aligned.m16n8k16.row.col.f32.bf16.bf16.f32 "
    "{%0,%1,%2,%3}, {%4,%5,%6,%7}, {%8,%9}, {%0,%1,%2,%3};"
    : "+f"(c[0]), "+f"(c[1]), "+f"(c[2]), "+f"(c[3])
    : "r"(a[0]), "r"(a[1]), "r"(a[2]), "r"(a[3]), "r"(b0), "r"(b1));
}
__device__ __forceinline__ void split_bf16(float f, __nv_bfloat16& h, __nv_bfloat16& l){
  h = __float2bfloat16(f);
  l = __float2bfloat16(f - __bfloat162float(h));
}

// ---------------- 1) adjacency (fp32 + bf16 hi/lo) ----------------
__global__ void k_adj(const float* __restrict__ E){
  int i = blockIdx.x, j = threadIdx.x;
  __shared__ float Ei[16];
  __shared__ float red[512];
  if (j < 16) Ei[j] = E[i*16 + j];
  __syncthreads();
  float d = 0.f;
  #pragma unroll
  for (int c = 0; c < 16; c++) d = fmaf(Ei[c], E[j*16 + c], d);
  d = fmaxf(d, 0.f);
  red[j] = d; __syncthreads();
  for (int s = 256; s > 0; s >>= 1){ if (j < s) red[j] = fmaxf(red[j], red[j+s]); __syncthreads(); }
  float mx = red[0];
  __syncthreads();
  float e = __expf(d - mx);
  red[j] = e; __syncthreads();
  for (int s = 256; s > 0; s >>= 1){ if (j < s) red[j] += red[j+s]; __syncthreads(); }
  float a = e * (1.f / red[0]);
  g_Af[i*512 + j] = a;
  __nv_bfloat16 h, l; split_bf16(a, h, l);
  g_Ah[i*512 + j] = h; g_Al[i*512 + j] = l;
}

// ---------------- 1b) M2 = 2*A@A -> bf16 hi/lo ----------------
__global__ void k_a2(){
  int row0 = blockIdx.x * 128, col0 = blockIdx.y * 64;
  __shared__ float As[128][17];
  __shared__ __align__(16) float Bs[16][64];
  int tid = threadIdx.x;
  int tx = tid & 7, ty = tid >> 3;
  float acc[8][8];
  #pragma unroll
  for (int i=0;i<8;i++)
    #pragma unroll
    for (int j=0;j<8;j++) acc[i][j] = 0.f;
  for (int k0 = 0; k0 < 512; k0 += 16){
    #pragma unroll
    for (int i = 0; i < 4; i++){
      int idx = tid + i*128;
      int r = idx >> 2, kq = idx & 3;
      float4 a4 = *(const float4*)(g_Af + (size_t)(row0 + r)*512 + k0 + kq*4);
      As[r][kq*4+0]=a4.x; As[r][kq*4+1]=a4.y; As[r][kq*4+2]=a4.z; As[r][kq*4+3]=a4.w;
    }
    #pragma unroll
    for (int i = 0; i < 2; i++){
      int idx = tid + i*128;
      int r = idx >> 4, cq = idx & 15;
      float4 b4 = *(const float4*)(g_Af + (size_t)(k0 + r)*512 + col0 + cq*4);
      *(float4*)&Bs[r][cq*4] = b4;
    }
    __syncthreads();
    #pragma unroll
    for (int k = 0; k < 16; k++){
      float a[8], b[8];
      #pragma unroll
      for (int i=0;i<8;i++) a[i] = As[ty*8+i][k];
      float4 b0 = *(const float4*)&Bs[k][tx*8];
      float4 b1 = *(const float4*)&Bs[k][tx*8+4];
      b[0]=b0.x; b[1]=b0.y; b[2]=b0.z; b[3]=b0.w;
      b[4]=b1.x; b[5]=b1.y; b[6]=b1.z; b[7]=b1.w;
      #pragma unroll
      for (int i=0;i<8;i++)
        #pragma unroll
        for (int j=0;j<8;j++) acc[i][j] = fmaf(a[i], b[j], acc[i][j]);
    }
    __syncthreads();
  }
  #pragma unroll
  for (int i=0;i<8;i++){
    size_t r = row0 + ty*8 + i;
    #pragma unroll
    for (int j=0;j<8;j++){
      float v = 2.f * acc[i][j];
      __nv_bfloat16 h, l; split_bf16(v, h, l);
      g_M2h[r*512 + col0 + tx*8 + j] = h;
      g_M2l[r*512 + col0 + tx*8 + j] = l;
    }
  }
}

// ---------------- 2) fused prep + qkvu + attention -> de (fp32 + bf16 hi/lo) ----------------
constexpr int QA_OX  = 0;
constexpr int QA_OB  = 4352;
constexpr int QA_OQ  = 8704;
constexpr int QA_OPQ = 25344;
constexpr int QA_OPK = 26112;
constexpr int QA_OPV = 26176;
constexpr int QA_OES = 26240;
constexpr int QA_SMB = 27008 * 4;

__global__ void __launch_bounds__(256, 2) k_qa(
    const float* __restrict__ hn, const float* __restrict__ ne1, const float* __restrict__ ne2,
    const float* __restrict__ Wq, const float* __restrict__ bq,
    const float* __restrict__ Wk, const float* __restrict__ bk,
    const float* __restrict__ Wv, const float* __restrict__ bv,
    const float* __restrict__ taw, const float* __restrict__ tab){
  extern __shared__ float sm[];
  float* Xs = sm + QA_OX;
  float* Bs = sm + QA_OB;
  float* Q  = sm + QA_OQ;
  float* pq = sm + QA_OPQ;
  float* pk = sm + QA_OPK;
  float* pv = sm + QA_OPV;
  float* es = sm + QA_OES;
  int tid = threadIdx.x;
  int bn0 = blockIdx.x * 64;
  int b = bn0 >> 9;

  #pragma unroll
  for (int i = tid; i < 64*16; i += 256){
    int r = i >> 4, q = i & 15;
    float4 v = *(const float4*)(hn + (size_t)(bn0 + r)*64 + q*4);
    Xs[r*68 + q*4+0]=v.x; Xs[r*68 + q*4+1]=v.y; Xs[r*68 + q*4+2]=v.z; Xs[r*68 + q*4+3]=v.w;
  }
  const float* e1 = ne1 + (size_t)(b*12 + 11)*32;
  if (tid < 64){
    float a = bk[tid];
    #pragma unroll
    for (int d = 0; d < 32; d++) a = fmaf(e1[d], Wk[d*64 + tid], a);
    pk[tid] = a;
  } else if (tid < 128){
    int o = tid - 64;
    float a = bv[o];
    #pragma unroll
    for (int d = 0; d < 32; d++) a = fmaf(e1[d], Wv[d*64 + o], a);
    pv[o] = a;
  }
  for (int i = tid; i < 768; i += 256){
    int t = i >> 6, o = i & 63;
    const float* e2 = ne2 + (size_t)(b*12 + t)*32;
    float a = bq[o];
    #pragma unroll
    for (int d = 0; d < 32; d++) a = fmaf(e2[d], Wq[d*64 + o], a);
    pq[t*64 + o] = a;
  }
  __syncthreads();

  int ty = tid >> 4, tx = tid & 15;
  for (int mode = 0; mode < 4; mode++){
    const float* Wsrc = (mode==0) ? Wq + 2048 : (mode==1) ? Wk + 2048
                      : (mode==2) ? Wv + 2048 : taw;
    #pragma unroll
    for (int i = tid; i < 64*16; i += 256){
      int r = i >> 4, q = i & 15;
      float4 w4 = *(const float4*)(Wsrc + (size_t)r*64 + q*4);
      Bs[r*68 + q*4+0]=w4.x; Bs[r*68 + q*4+1]=w4.y; Bs[r*68 + q*4+2]=w4.z; Bs[r*68 + q*4+3]=w4.w;
    }
    __syncthreads();
    float acc[4][4];
    #pragma unroll
    for (int i=0;i<4;i++){ acc[i][0]=0.f; acc[i][1]=0.f; acc[i][2]=0.f; acc[i][3]=0.f; }
    #pragma unroll 16
    for (int k = 0; k < 64; k++){
      float a[4], bb[4];
      #pragma unroll
      for (int i=0;i<4;i++) a[i] = Xs[(ty*4+i)*68 + k];
      #pragma unroll
      for (int j=0;j<4;j++) bb[j] = Bs[k*68 + tx*4+j];
      #pragma unroll
      for (int i=0;i<4;i++)
        #pragma unroll
        for (int j=0;j<4;j++) acc[i][j] = fmaf(a[i], bb[j], acc[i][j]);
    }
    #pragma unroll
    for (int i=0;i<4;i++){
      int r = ty*4 + i;
      #pragma unroll
      for (int j=0;j<4;j++){
        int c = tx*4 + j;
        float v = acc[i][j];
        if (mode == 1)      v = fmaxf(v + pk[c], 0.f);
        else if (mode == 2) v = fmaxf(v + pv[c], 0.f);
        else if (mode == 3) v = v + tab[c];
        Q[r*260 + mode*64 + c] = v;
      }
    }
    __syncthreads();
  }
  for (int i = tid; i < 4096; i += 256) Bs[(i>>6)*68 + (i&63)] = taw[4096 + i];
  __syncthreads();

  int w = tid >> 5, lane = tid & 31;
  float* esw = es + w*96;
  int c0 = lane*2;
  for (int i = 0; i < 8; i++){
    int lr = w*8 + i;
    int n = (bn0 + lr) & 511;
    const float* q_ = Q + lr*260;
    float u0 = q_[192+c0], u1 = q_[193+c0];
    float vw0[8], vw1[8];
    #pragma unroll
    for (int d = 0; d < 8; d++){
      float a0 = 0.f, a1 = 0.f;
      #pragma unroll
      for (int cp = 0; cp < 8; cp++){
        float vv = q_[128 + d*8 + cp];
        float2 t2 = *(const float2*)&Bs[(d*8+cp)*68 + c0];
        a0 = fmaf(vv, t2.x, a0); a1 = fmaf(vv, t2.y, a1);
      }
      vw0[d] = a0; vw1[d] = a1;
    }
    for (int task = lane; task < 96; task += 32){
      int d = task / 12, t = task - d*12;
      const float* pqd = pq + t*64 + d*8;
      float e = 0.f;
      #pragma unroll
      for (int cp = 0; cp < 8; cp++){
        float qv = fmaxf(q_[d*8+cp] + pqd[cp], 0.f);
        e = fmaf(qv, q_[64 + d*8 + cp], e);
      }
      esw[d*12 + t] = e;
    }
    __syncwarp();
    if (lane < 8){
      float mx = -1e30f;
      #pragma unroll
      for (int t=0;t<12;t++) mx = fmaxf(mx, esw[lane*12 + t]);
      float ssum = 0.f;
      #pragma unroll
      for (int t=0;t<12;t++){ float ex = __expf(esw[lane*12+t]-mx); esw[lane*12+t]=ex; ssum+=ex; }
      float inv = 1.f/ssum;
      #pragma unroll
      for (int t=0;t<12;t++) esw[lane*12+t] *= inv;
    }
    __syncwarp();
    #pragma unroll
    for (int t = 0; t < 12; t++){
      float o0 = u0, o1 = u1;
      #pragma unroll
      for (int d = 0; d < 8; d++){
        float a = esw[d*12 + t];
        o0 = fmaf(a, vw0[d], o0); o1 = fmaf(a, vw1[d], o1);
      }
      size_t off = ((size_t)(b*12 + t)*512 + n)*64;
      *(float2*)(g_de + off + c0) = make_float2(o0, o1);
      __nv_bfloat16 h0,l0,h1,l1;
      split_bf16(o0,h0,l0); split_bf16(o1,h1,l1);
      __nv_bfloat162 hv; hv.x=h0; hv.y=h1;
      __nv_bfloat162 lv; lv.x=l0; lv.y=l1;
      *(__nv_bfloat162*)(g_deh + off + c0) = hv;
      *(__nv_bfloat162*)(g_del + off + c0) = lv;
    }
    __syncwarp();
  }
}

// ---------------- 3) weight gen ----------------
__global__ void k_wgen(const float* __restrict__ Am, const float* __restrict__ Bw,
                       const float* __restrict__ g, int Nc, int dst){
  int col0 = blockIdx.x * 64, row0 = blockIdx.y * 64;
  __shared__ float As[64][33];
  __shared__ float Bs[32][65];
  int tid = threadIdx.x;
  #pragma unroll
  for (int i = 0; i < 2; i++){
    int idx = tid + i*256;
    { int r = idx >> 3, kq = idx & 7;
      float4 a4 = *(const float4*)(Am + (size_t)(row0 + r)*32 + kq*4);
      As[r][kq*4+0]=a4.x; As[r][kq*4+1]=a4.y; As[r][kq*4+2]=a4.z; As[r][kq*4+3]=a4.w; }
    { int r = idx >> 4, cq = idx & 15;
      float4 b4 = *(const float4*)(Bw + (size_t)r*Nc + col0 + cq*4);
      Bs[r][cq*4+0]=b4.x; Bs[r][cq*4+1]=b4.y; Bs[r][cq*4+2]=b4.z; Bs[r][cq*4+3]=b4.w; }
  }
  __syncthreads();
  int ty = tid >> 4, tx = tid & 15;
  float acc[4][4];
  #pragma unroll
  for (int i=0;i<4;i++){ acc[i][0]=0.f; acc[i][1]=0.f; acc[i][2]=0.f; acc[i][3]=0.f; }
  #pragma unroll
  for (int k = 0; k < 32; k++){
    float a[4], b[4];
    #pragma unroll
    for (int i=0;i<4;i++) a[i] = As[ty*4+i][k];
    #pragma unroll
    for (int j=0;j<4;j++) b[j] = Bs[k][tx*4+j];
    #pragma unroll
    for (int i=0;i<4;i++)
      #pragma unroll
      for (int j=0;j<4;j++) acc[i][j] = fmaf(a[i], b[j], acc[i][j]);
  }
  int No = (dst==0) ? 128 : 64;
  int GNo = 65*No;
  #pragma unroll
  for (int i=0;i<4;i++){
    int r = row0 + ty*4 + i;
    #pragma unroll
    for (int j=0;j<4;j++){
      int c = col0 + tx*4 + j;
      float v = acc[i][j] + g[c];
      if (dst == 2)      g_b1[(size_t)r*128 + c] = v;
      else if (dst == 3) g_bu[(size_t)r*64 + c] = v;
      else {
        int seg = c / GNo, rem = c - seg*GNo;
        int ki = rem / No, o = rem - ki*No;
        if (ki >= 1){
          size_t off = (((size_t)r*3 + seg)*64 + (ki-1))*No + o;
          __nv_bfloat16 h, l; split_bf16(v, h, l);
          if (dst == 0){ g_W1h[off] = h; g_W1l[off] = l; }
          else         { g_Wuh[off] = h; g_Wul[off] = l; }
        }
      }
    }
  }
}

// ---------------- 4) dual HMMA: y1 = A@X, y2 = M2@X - X (512 thr, 16 warps, 3-stage) ----------------
constexpr int STG_SZ = 29184;
constexpr int OAH = 0, OAL = 6144, OMH = 12288, OML = 18432, OXH = 24576, OXL = 26880;
constexpr int SMB = 3 * STG_SZ;   // 87552

__global__ void __launch_bounds__(512, 2) k_bmma2(int from_yz){
  extern __shared__ __align__(16) char dyn[];
  uint32_t sb = s2u(dyn);
  const __nv_bfloat16* __restrict__ Xh = from_yz ? g_yzh : g_deh;
  const __nv_bfloat16* __restrict__ Xl = from_yz ? g_yzl : g_del;
  const float* __restrict__ Z = from_yz ? g_yz : g_de;

  int bt = blockIdx.y, m0 = blockIdx.x * 128;
  int tid = threadIdx.x, wid = tid >> 5, lane = tid & 31;
  int warp_m = wid >> 1, warp_n = wid & 1;   // 8 x 2

  // loads: 4 groups of 128 threads each own one A-array; threads <256 also load X
  int grp = tid >> 7;            // 0:Ah 1:Al 2:M2h 3:M2l
  int arow = tid & 127;
  const __nv_bfloat16* Asrc = grp==0 ? g_Ah : grp==1 ? g_Al : grp==2 ? g_M2h : g_M2l;
  uint32_t aoffc = (grp==0 ? OAH : grp==1 ? OAL : grp==2 ? OMH : OML) + (uint32_t)arow*48;
  int xr = (tid & 127) >> 3, xq = tid & 7;
  bool xload = tid < 256, xhi = tid < 128;

  auto load_chunk = [&](int c, int st){
    uint32_t base = sb + (uint32_t)st * STG_SZ;
    int k0 = c * 16;
    size_t ga = (size_t)(m0 + arow)*512 + k0;
    cp16(base + aoffc,      Asrc + ga);
    cp16(base + aoffc + 16, Asrc + ga + 8);
    if (xload){
      size_t gx = ((size_t)bt*512 + k0 + xr)*64 + xq*8;
      uint32_t xo = (xhi ? OXH : OXL) + (uint32_t)xr*144 + xq*16;
      cp16(base + xo, (xhi ? Xh : Xl) + gx);
    }
  };

  float acc1[4][4], acc2[4][4];
  #pragma unroll
  for (int nn=0;nn<4;nn++)
    #pragma unroll
    for (int j=0;j<4;j++){ acc1[nn][j] = 0.f; acc2[nn][j] = 0.f; }

  load_chunk(0, 0);
  asm volatile("cp.async.commit_group;" ::: "memory");
  load_chunk(1, 1);
  asm volatile("cp.async.commit_group;" ::: "memory");

  uint32_t lrow = lane & 15;
  uint32_t lk = (lane >> 4) << 4;

  for (int c = 0; c < 32; c++){
    if (c < 31) asm volatile("cp.async.wait_group 1;" ::: "memory");
    else        asm volatile("cp.async.wait_group 0;" ::: "memory");
    __syncthreads();

    int st = c % 3;
    uint32_t base = sb + (uint32_t)st * STG_SZ;
    uint32_t aoff = (uint32_t)(warp_m*16 + lrow)*48 + lk;
    uint32_t boff = lrow*144 + (uint32_t)warp_n*64 + lk;

    uint32_t bh[2][4], bl[2][4];
    #pragma unroll
    for (int np = 0; np < 2; np++){
      ldm_x4t(bh[np], base + OXH + boff + np*32);
      ldm_x4t(bl[np], base + OXL + boff + np*32);
    }
    {
      uint32_t fh[4], fl[4];
      ldm_x4(fh, base + OAH + aoff);
      ldm_x4(fl, base + OAL + aoff);
      #pragma unroll
      for (int nn = 0; nn < 4; nn++){
        int np = nn >> 1, sub = (nn & 1) * 2;
        mma_bf16(acc1[nn], fh, bh[np][sub], bh[np][sub+1]);
        mma_bf16(acc1[nn], fh, bl[np][sub], bl[np][sub+1]);
        mma_bf16(acc1[nn], fl, bh[np][sub], bh[np][sub+1]);
      }
    }
    {
      uint32_t fh[4], fl[4];
      ldm_x4(fh, base + OMH + aoff);
      ldm_x4(fl, base + OML + aoff);
      #pragma unroll
      for (int nn = 0; nn < 4; nn++){
        int np = nn >> 1, sub = (nn & 1) * 2;
        mma_bf16(acc2[nn], fh, bh[np][sub], bh[np][sub+1]);
        mma_bf16(acc2[nn], fh, bl[np][sub], bl[np][sub+1]);
        mma_bf16(acc2[nn], fl, bh[np][sub], bh[np][sub+1]);
      }
    }
    if (c + 2 < 32){
      load_chunk(c + 2, (c + 2) % 3);
      asm volatile("cp.async.commit_group;" ::: "memory");
    }
  }

  int rbase = m0 + warp_m*16 + (lane >> 2);
  int cbase = warp_n*32 + (lane & 3)*2;
  #pragma unroll
  for (int nn = 0; nn < 4; nn++){
    int col = cbase + nn*8;
    #pragma unroll
    for (int half = 0; half < 2; half++){
      int row = rbase + half*8;
      size_t off = ((size_t)bt*512 + row)*64 + col;
      float v0 = acc1[nn][half*2], v1 = acc1[nn][half*2+1];
      __nv_bfloat16 h0,l0,h1,l1;
      split_bf16(v0,h0,l0); split_bf16(v1,h1,l1);
      __nv_bfloat162 hv; hv.x=h0; hv.y=h1;
      __nv_bfloat162 lv; lv.x=l0; lv.y=l1;
      *(__nv_bfloat162*)(g_y1h + off) = hv;
      *(__nv_bfloat162*)(g_y1l + off) = lv;
      float2 z = *(const float2*)(Z + off);
      float w0 = acc2[nn][half*2] - z.x;
      float w1 = acc2[nn][half*2+1] - z.y;
      split_bf16(w0,h0,l0); split_bf16(w1,h1,l1);
      hv.x=h0; hv.y=h1; lv.x=l0; lv.y=l1;
      *(__nv_bfloat162*)(g_y2h + off) = hv;
      *(__nv_bfloat162*)(g_y2l + off) = lv;
    }
  }
}

// ---------------- 5) HMMA combine GEMM: act([Y0|Y1|Y2] @ W[bt] + b) ----------------
template<int WHICH>
__global__ void __launch_bounds__(256, 2) k_combT(){
  constexpr int No = WHICH ? 64 : 128;
  const __nv_bfloat16* __restrict__ Y0h = WHICH ? g_yzh : g_deh;
  const __nv_bfloat16* __restrict__ Y0l = WHICH ? g_yzl : g_del;
  const __nv_bfloat16* __restrict__ Wh  = WHICH ? g_Wuh : g_W1h;
  const __nv_bfloat16* __restrict__ Wl  = WHICH ? g_Wul : g_W1l;

  __shared__ __nv_bfloat16 sAh[2][128*24], sAl[2][128*24];
  __shared__ __nv_bfloat16 sXh[2][16*72],  sXl[2][16*72];

  int bt = blockIdx.z, n0 = blockIdx.y * 128, ct = blockIdx.x;
  int tid = threadIdx.x, wid = tid >> 5, lane = tid & 31;
  int warp_m = wid >> 1, warp_n = wid & 1;

  uint32_t uAh[2] = { s2u(sAh[0]), s2u(sAh[1]) };
  uint32_t uAl[2] = { s2u(sAl[0]), s2u(sAl[1]) };
  uint32_t uXh[2] = { s2u(sXh[0]), s2u(sXh[1]) };
  uint32_t uXl[2] = { s2u(sXl[0]), s2u(sXl[1]) };

  int arow = tid >> 1, aq = tid & 1;
  int xr = (tid & 127) >> 3, xq = tid & 7;
  bool xhi = tid < 128;

  auto load_chunk = [&](int c, int buf){
    int seg = c >> 2, kin0 = (c & 3) * 16;
    const __nv_bfloat16* Yh = seg==0 ? Y0h : seg==1 ? g_y1h : g_y2h;
    const __nv_bfloat16* Yl = seg==0 ? Y0l : seg==1 ? g_y1l : g_y2l;
    size_t ga = ((size_t)bt*512 + n0 + arow)*64 + kin0 + aq*8;
    cp16(uAh[buf] + arow*48 + aq*16, Yh + ga);
    cp16(uAl[buf] + arow*48 + aq*16, Yl + ga);
    size_t gw = (((size_t)bt*3 + seg)*64 + kin0 + xr)*No + ct*64 + xq*8;
    if (xhi) cp16(uXh[buf] + xr*144 + xq*16, Wh + gw);
    else     cp16(uXl[buf] + xr*144 + xq*16, Wl + gw);
  };

  float acc[2][4][4];
  #pragma unroll
  for (int mi=0;mi<2;mi++)
    #pragma unroll
    for (int nn=0;nn<4;nn++)
      #pragma unroll
      for (int j=0;j<4;j++) acc[mi][nn][j] = 0.f;

  load_chunk(0, 0);
  asm volatile("cp.async.commit_group;" ::: "memory");

  uint32_t lrow = lane & 15;
  uint32_t lk = (lane >> 4) << 4;

  for (int c = 0; c < 12; c++){
    int buf = c & 1;
    if (c < 11){
      load_chunk(c + 1, buf ^ 1);
      asm volatile("cp.async.commit_group;" ::: "memory");
      asm volatile("cp.async.wait_group 1;" ::: "memory");
    } else {
      asm volatile("cp.async.wait_group 0;" ::: "memory");
    }
    __syncthreads();

    uint32_t ah[2][4], al[2][4], bh[2][4], bl[2][4];
    #pragma unroll
    for (int mi = 0; mi < 2; mi++){
      uint32_t aoff = (uint32_t)(warp_m*32 + mi*16 + lrow)*48 + lk;
      ldm_x4(ah[mi], uAh[buf] + aoff);
      ldm_x4(al[mi], uAl[buf] + aoff);
    }
    #pragma unroll
    for (int np = 0; np < 2; np++){
      uint32_t boff = lrow*144 + (uint32_t)(warp_n*32 + np*16)*2 + lk;
      ldm_x4t(bh[np], uXh[buf] + boff);
      ldm_x4t(bl[np], uXl[buf] + boff);
    }
    #pragma unroll
    for (int mi = 0; mi < 2; mi++){
      #pragma unroll
      for (int nn = 0; nn < 4; nn++){
        int np = nn >> 1, sub = (nn & 1) * 2;
        mma_bf16(acc[mi][nn], ah[mi], bh[np][sub], bh[np][sub+1]);
        mma_bf16(acc[mi][nn], ah[mi], bl[np][sub], bl[np][sub+1]);
        mma_bf16(acc[mi][nn], al[mi], bh[np][sub], bh[np][sub+1]);
      }
    }
    __syncthreads();
  }

  int rbase = n0 + warp_m*32 + (lane >> 2);
  int cbase = warp_n*32 + (lane & 3)*2;
  #pragma unroll
  for (int mi = 0; mi < 2; mi++){
    #pragma unroll
    for (int nn = 0; nn < 4; nn++){
      int col = cbase + nn*8;
      int gcol = ct*64 + col;
      #pragma unroll
      for (int half = 0; half < 2; half++){
        int row = rbase + mi*16 + half*8;
        size_t off = ((size_t)bt*512 + row)*64 + col;
        float v0 = acc[mi][nn][half*2], v1 = acc[mi][nn][half*2+1];
        if (WHICH == 0){
          v0 += g_b1[(size_t)bt*128 + gcol];
          v1 += g_b1[(size_t)bt*128 + gcol + 1];
          v0 = 1.f/(1.f + __expf(-v0));
          v1 = 1.f/(1.f + __expf(-v1));
          if (ct == 0){
            float2 de = *(const float2*)(g_de + off);
            float z0 = v0 * de.x, z1 = v1 * de.y;
            *(float2*)(g_yz + off) = make_float2(z0, z1);
            __nv_bfloat16 h0,l0,h1,l1;
            split_bf16(z0,h0,l0); split_bf16(z1,h1,l1);
            __nv_bfloat162 hv; hv.x=h0; hv.y=h1;
            __nv_bfloat162 lv; lv.x=l0; lv.y=l1;
            *(__nv_bfloat162*)(g_yzh + off) = hv;
            *(__nv_bfloat162*)(g_yzl + off) = lv;
          } else {
            *(float2*)(g_rg + off) = make_float2(v0, v1);
          }
        } else {
          v0 = tanhf(v0 + g_bu[(size_t)bt*64 + gcol]);
          v1 = tanhf(v1 + g_bu[(size_t)bt*64 + gcol + 1]);
          *(float2*)(g_hc + off) = make_float2(v0, v1);
        }
      }
    }
  }
}

// ---------------- 6) final projection ----------------
__global__ void k_out(const float* __restrict__ outw, const float* __restrict__ outb,
                      float* __restrict__ out){
  int gw = blockIdx.x*8 + (threadIdx.x >> 5);
  int lane = threadIdx.x & 31;
  size_t mn = (size_t)gw;
  int m = gw >> 9;
  int t = m % 12;
  size_t base = mn << 6;
  float s = 0.f;
  #pragma unroll
  for (int ii = 0; ii < 2; ii++){
    int i = lane + ii*32;
    float rg = g_rg[base + i];
    float de = g_de[base + i];
    float hc = g_hc[base + i];
    float st = fmaf(rg, de - hc, hc);
    s = fmaf(st, outw[t*64 + i], s);
  }
  #pragma unroll
  for (int off = 16; off > 0; off >>= 1) s += __shfl_xor_sync(0xffffffffu, s, off);
  if (lane == 0) out[mn] = s + outb[t];
}

// ---------------- launch ----------------
extern "C" void kernel_launch(void* const* d_in, const int* in_sizes, int n_in,
                              void* d_out, int out_size){
  (void)in_sizes; (void)n_in; (void)out_size;
  const float* hn  = (const float*)d_in[2];
  const float* ne1 = (const float*)d_in[3];
  const float* ne2 = (const float*)d_in[4];
  const float* E   = (const float*)d_in[5];
  const float* Wq  = (const float*)d_in[6];
  const float* bq  = (const float*)d_in[7];
  const float* Wk  = (const float*)d_in[8];
  const float* bk  = (const float*)d_in[9];
  const float* Wv  = (const float*)d_in[10];
  const float* bv  = (const float*)d_in[11];
  const float* taw = (const float*)d_in[12];
  const float* tab = (const float*)d_in[13];
  const float* gwp = (const float*)d_in[14];
  const float* gw  = (const float*)d_in[15];
  const float* gbp = (const float*)d_in[16];
  const float* gb  = (const float*)d_in[17];
  const float* uwp = (const float*)d_in[18];
  const float* uw  = (const float*)d_in[19];
  const float* ubp = (const float*)d_in[20];
  const float* ub  = (const float*)d_in[21];
  const float* outw= (const float*)d_in[22];
  const float* outb= (const float*)d_in[23];
  float* out = (float*)d_out;

  cudaFuncSetAttribute(k_bmma2, cudaFuncAttributeMaxDynamicSharedMemorySize, SMB);
  cudaFuncSetAttribute(k_qa, cudaFuncAttributeMaxDynamicSharedMemorySize, QA_SMB);

  k_adj<<<512, 512>>>(E);
  k_a2<<<dim3(4, 8), 128>>>();
  k_qa<<<512, 256, QA_SMB>>>(hn, ne1, ne2, Wq, bq, Wk, bk, Wv, bv, taw, tab);
  k_bmma2<<<dim3(4, 768), 512, SMB>>>(0);        // 4 (profiled)
  k_wgen<<<dim3(390, 12), 256>>>(ne2, gwp, gw, 24960, 0);
  k_wgen<<<dim3(195, 12), 256>>>(ne2, uwp, uw, 12480, 1);
  k_wgen<<<dim3(2, 12), 256>>>(ne2, gbp, gb, 128, 2);
  k_wgen<<<dim3(1, 12), 256>>>(ne2, ubp, ub, 64, 3);
  k_combT<0><<<dim3(2, 4, 768), 256>>>();        // yz / rg
  k_bmma2<<<dim3(4, 768), 512, SMB>>>(1);
  k_combT<1><<<dim3(1, 4, 768), 256>>>();        // hc
  k_out<<<49152, 256>>>(outw, outb, out);
}

// round 10
// speedup vs baseline: 1.7911x; 1.7911x over previous
#include <cuda_runtime.h>
#include <cuda_fp16.h>
#include <math.h>
#include <stdint.h>

// B=64, T=12, N=512, H=64, TD=32, ED=16, CHEB_K=3, D_HEADS=8, M=768
constexpr size_t NF = (size_t)768*512*64;

// ---------------- device scratch ----------------
__device__ float g_Af32[512*512];
__device__ __half g_Af[512*512], g_M2f[512*512];
__device__ float g_de[NF], g_yz[NF], g_hc[NF], g_rg[NF];
__device__ __half g_def[NF], g_y1f[NF], g_y2f[NF], g_yzf[NF];
__device__ __half g_W1f[(size_t)768*3*64*128];
__device__ __half g_Wuf[(size_t)768*3*64*64];
__device__ float g_b1[768*128], g_bu[768*64];

// ---------------- ptx helpers (sm_80+ baseline only) ----------------
__device__ __forceinline__ uint32_t s2u(const void* p){
  uint32_t a;
  asm("{ .reg .u64 t; cvta.to.shared.u64 t, %1; cvt.u32.u64 %0, t; }" : "=r"(a) : "l"(p));
  return a;
}
__device__ __forceinline__ void cp16(uint32_t dst, const void* src){
  asm volatile("cp.async.cg.shared.global [%0], [%1], 16;" :: "r"(dst), "l"(src) : "memory");
}
__device__ __forceinline__ void ldm_x4(uint32_t* r, uint32_t addr){
  asm volatile("ldmatrix.sync.aligned.m8n8.x4.shared.b16 {%0,%1,%2,%3}, [%4];"
    : "=r"(r[0]), "=r"(r[1]), "=r"(r[2]), "=r"(r[3]) : "r"(addr));
}
__device__ __forceinline__ void ldm_x4t(uint32_t* r, uint32_t addr){
  asm volatile("ldmatrix.sync.aligned.m8n8.x4.trans.shared.b16 {%0,%1,%2,%3}, [%4];"
    : "=r"(r[0]), "=r"(r[1]), "=r"(r[2]), "=r"(r[3]) : "r"(addr));
}
__device__ __forceinline__ void mma_f16(float* c, const uint32_t* a, uint32_t b0, uint32_t b1){
  asm volatile(
    "mma.sync.aligned.m16n8k16.row.col.f32.f16.f16.f32 "
    "{%0,%1,%2,%3}, {%4,%5,%6,%7}, {%8,%9}, {%0,%1,%2,%3};"
    : "+f"(c[0]), "+f"(c[1]), "+f"(c[2]), "+f"(c[3])
    : "r"(a[0]), "r"(a[1]), "r"(a[2]), "r"(a[3]), "r"(b0), "r"(b1));
}

// ---------------- 1) adjacency (fp32 + fp16) ----------------
__global__ void k_adj(const float* __restrict__ E){
  int i = blockIdx.x, j = threadIdx.x;
  __shared__ float Ei[16];
  __shared__ float red[512];
  if (j < 16) Ei[j] = E[i*16 + j];
  __syncthreads();
  float d = 0.f;
  #pragma unroll
  for (int c = 0; c < 16; c++) d = fmaf(Ei[c], E[j*16 + c], d);
  d = fmaxf(d, 0.f);
  red[j] = d; __syncthreads();
  for (int s = 256; s > 0; s >>= 1){ if (j < s) red[j] = fmaxf(red[j], red[j+s]); __syncthreads(); }
  float mx = red[0];
  __syncthreads();
  float e = __expf(d - mx);
  red[j] = e; __syncthreads();
  for (int s = 256; s > 0; s >>= 1){ if (j < s) red[j] += red[j+s]; __syncthreads(); }
  float a = e * (1.f / red[0]);
  g_Af32[i*512 + j] = a;
  g_Af[i*512 + j] = __float2half_rn(a);
}

// ---------------- 1b) M2 = 2*A@A -> fp16 ----------------
__global__ void k_a2(){
  int row0 = blockIdx.x * 128, col0 = blockIdx.y * 64;
  __shared__ float As[128][17];
  __shared__ __align__(16) float Bs[16][64];
  int tid = threadIdx.x;
  int tx = tid & 7, ty = tid >> 3;
  float acc[8][8];
  #pragma unroll
  for (int i=0;i<8;i++)
    #pragma unroll
    for (int j=0;j<8;j++) acc[i][j] = 0.f;
  for (int k0 = 0; k0 < 512; k0 += 16){
    #pragma unroll
    for (int i = 0; i < 4; i++){
      int idx = tid + i*128;
      int r = idx >> 2, kq = idx & 3;
      float4 a4 = *(const float4*)(g_Af32 + (size_t)(row0 + r)*512 + k0 + kq*4);
      As[r][kq*4+0]=a4.x; As[r][kq*4+1]=a4.y; As[r][kq*4+2]=a4.z; As[r][kq*4+3]=a4.w;
    }
    #pragma unroll
    for (int i = 0; i < 2; i++){
      int idx = tid + i*128;
      int r = idx >> 4, cq = idx & 15;
      float4 b4 = *(const float4*)(g_Af32 + (size_t)(k0 + r)*512 + col0 + cq*4);
      *(float4*)&Bs[r][cq*4] = b4;
    }
    __syncthreads();
    #pragma unroll
    for (int k = 0; k < 16; k++){
      float a[8], b[8];
      #pragma unroll
      for (int i=0;i<8;i++) a[i] = As[ty*8+i][k];
      float4 b0 = *(const float4*)&Bs[k][tx*8];
      float4 b1 = *(const float4*)&Bs[k][tx*8+4];
      b[0]=b0.x; b[1]=b0.y; b[2]=b0.z; b[3]=b0.w;
      b[4]=b1.x; b[5]=b1.y; b[6]=b1.z; b[7]=b1.w;
      #pragma unroll
      for (int i=0;i<8;i++)
        #pragma unroll
        for (int j=0;j<8;j++) acc[i][j] = fmaf(a[i], b[j], acc[i][j]);
    }
    __syncthreads();
  }
  #pragma unroll
  for (int i=0;i<8;i++){
    size_t r = row0 + ty*8 + i;
    #pragma unroll
    for (int j=0;j<8;j++)
      g_M2f[r*512 + col0 + tx*8 + j] = __float2half_rn(2.f * acc[i][j]);
  }
}

// ---------------- 2) fused prep + qkvu + attention -> de (fp32 + fp16) ----------------
constexpr int QA_OX  = 0;
constexpr int QA_OB  = 4352;
constexpr int QA_OQ  = 8704;
constexpr int QA_OPQ = 25344;
constexpr int QA_OPK = 26112;
constexpr int QA_OPV = 26176;
constexpr int QA_OES = 26240;
constexpr int QA_SMB = 27008 * 4;

__global__ void __launch_bounds__(256, 2) k_qa(
    const float* __restrict__ hn, const float* __restrict__ ne1, const float* __restrict__ ne2,
    const float* __restrict__ Wq, const float* __restrict__ bq,
    const float* __restrict__ Wk, const float* __restrict__ bk,
    const float* __restrict__ Wv, const float* __restrict__ bv,
    const float* __restrict__ taw, const float* __restrict__ tab){
  extern __shared__ float sm[];
  float* Xs = sm + QA_OX;
  float* Bs = sm + QA_OB;
  float* Q  = sm + QA_OQ;
  float* pq = sm + QA_OPQ;
  float* pk = sm + QA_OPK;
  float* pv = sm + QA_OPV;
  float* es = sm + QA_OES;
  int tid = threadIdx.x;
  int bn0 = blockIdx.x * 64;
  int b = bn0 >> 9;

  #pragma unroll
  for (int i = tid; i < 64*16; i += 256){
    int r = i >> 4, q = i & 15;
    float4 v = *(const float4*)(hn + (size_t)(bn0 + r)*64 + q*4);
    Xs[r*68 + q*4+0]=v.x; Xs[r*68 + q*4+1]=v.y; Xs[r*68 + q*4+2]=v.z; Xs[r*68 + q*4+3]=v.w;
  }
  const float* e1 = ne1 + (size_t)(b*12 + 11)*32;
  if (tid < 64){
    float a = bk[tid];
    #pragma unroll
    for (int d = 0; d < 32; d++) a = fmaf(e1[d], Wk[d*64 + tid], a);
    pk[tid] = a;
  } else if (tid < 128){
    int o = tid - 64;
    float a = bv[o];
    #pragma unroll
    for (int d = 0; d < 32; d++) a = fmaf(e1[d], Wv[d*64 + o], a);
    pv[o] = a;
  }
  for (int i = tid; i < 768; i += 256){
    int t = i >> 6, o = i & 63;
    const float* e2 = ne2 + (size_t)(b*12 + t)*32;
    float a = bq[o];
    #pragma unroll
    for (int d = 0; d < 32; d++) a = fmaf(e2[d], Wq[d*64 + o], a);
    pq[t*64 + o] = a;
  }
  __syncthreads();

  int ty = tid >> 4, tx = tid & 15;
  for (int mode = 0; mode < 4; mode++){
    const float* Wsrc = (mode==0) ? Wq + 2048 : (mode==1) ? Wk + 2048
                      : (mode==2) ? Wv + 2048 : taw;
    #pragma unroll
    for (int i = tid; i < 64*16; i += 256){
      int r = i >> 4, q = i & 15;
      float4 w4 = *(const float4*)(Wsrc + (size_t)r*64 + q*4);
      Bs[r*68 + q*4+0]=w4.x; Bs[r*68 + q*4+1]=w4.y; Bs[r*68 + q*4+2]=w4.z; Bs[r*68 + q*4+3]=w4.w;
    }
    __syncthreads();
    float acc[4][4];
    #pragma unroll
    for (int i=0;i<4;i++){ acc[i][0]=0.f; acc[i][1]=0.f; acc[i][2]=0.f; acc[i][3]=0.f; }
    #pragma unroll 16
    for (int k = 0; k < 64; k++){
      float a[4], bb[4];
      #pragma unroll
      for (int i=0;i<4;i++) a[i] = Xs[(ty*4+i)*68 + k];
      #pragma unroll
      for (int j=0;j<4;j++) bb[j] = Bs[k*68 + tx*4+j];
      #pragma unroll
      for (int i=0;i<4;i++)
        #pragma unroll
        for (int j=0;j<4;j++) acc[i][j] = fmaf(a[i], bb[j], acc[i][j]);
    }
    #pragma unroll
    for (int i=0;i<4;i++){
      int r = ty*4 + i;
      #pragma unroll
      for (int j=0;j<4;j++){
        int c = tx*4 + j;
        float v = acc[i][j];
        if (mode == 1)      v = fmaxf(v + pk[c], 0.f);
        else if (mode == 2) v = fmaxf(v + pv[c], 0.f);
        else if (mode == 3) v = v + tab[c];
        Q[r*260 + mode*64 + c] = v;
      }
    }
    __syncthreads();
  }
  for (int i = tid; i < 4096; i += 256) Bs[(i>>6)*68 + (i&63)] = taw[4096 + i];
  __syncthreads();

  int w = tid >> 5, lane = tid & 31;
  float* esw = es + w*96;
  int c0 = lane*2;
  for (int i = 0; i < 8; i++){
    int lr = w*8 + i;
    int n = (bn0 + lr) & 511;
    const float* q_ = Q + lr*260;
    float u0 = q_[192+c0], u1 = q_[193+c0];
    float vw0[8], vw1[8];
    #pragma unroll
    for (int d = 0; d < 8; d++){
      float a0 = 0.f, a1 = 0.f;
      #pragma unroll
      for (int cp = 0; cp < 8; cp++){
        float vv = q_[128 + d*8 + cp];
        float2 t2 = *(const float2*)&Bs[(d*8+cp)*68 + c0];
        a0 = fmaf(vv, t2.x, a0); a1 = fmaf(vv, t2.y, a1);
      }
      vw0[d] = a0; vw1[d] = a1;
    }
    for (int task = lane; task < 96; task += 32){
      int d = task / 12, t = task - d*12;
      const float* pqd = pq + t*64 + d*8;
      float e = 0.f;
      #pragma unroll
      for (int cp = 0; cp < 8; cp++){
        float qv = fmaxf(q_[d*8+cp] + pqd[cp], 0.f);
        e = fmaf(qv, q_[64 + d*8 + cp], e);
      }
      esw[d*12 + t] = e;
    }
    __syncwarp();
    if (lane < 8){
      float mx = -1e30f;
      #pragma unroll
      for (int t=0;t<12;t++) mx = fmaxf(mx, esw[lane*12 + t]);
      float ssum = 0.f;
      #pragma unroll
      for (int t=0;t<12;t++){ float ex = __expf(esw[lane*12+t]-mx); esw[lane*12+t]=ex; ssum+=ex; }
      float inv = 1.f/ssum;
      #pragma unroll
      for (int t=0;t<12;t++) esw[lane*12+t] *= inv;
    }
    __syncwarp();
    #pragma unroll
    for (int t = 0; t < 12; t++){
      float o0 = u0, o1 = u1;
      #pragma unroll
      for (int d = 0; d < 8; d++){
        float a = esw[d*12 + t];
        o0 = fmaf(a, vw0[d], o0); o1 = fmaf(a, vw1[d], o1);
      }
      size_t off = ((size_t)(b*12 + t)*512 + n)*64;
      *(float2*)(g_de + off + c0) = make_float2(o0, o1);
      __half2 hv; hv.x = __float2half_rn(o0); hv.y = __float2half_rn(o1);
      *(__half2*)(g_def + off + c0) = hv;
    }
    __syncwarp();
  }
}

// ---------------- 3) weight gen -> fp16 W (dead row-0 dropped) + fp32 biases ----------------
__global__ void k_wgen(const float* __restrict__ Am, const float* __restrict__ Bw,
                       const float* __restrict__ g, int Nc, int dst){
  int col0 = blockIdx.x * 64, row0 = blockIdx.y * 64;
  __shared__ float As[64][33];
  __shared__ float Bs[32][65];
  int tid = threadIdx.x;
  #pragma unroll
  for (int i = 0; i < 2; i++){
    int idx = tid + i*256;
    { int r = idx >> 3, kq = idx & 7;
      float4 a4 = *(const float4*)(Am + (size_t)(row0 + r)*32 + kq*4);
      As[r][kq*4+0]=a4.x; As[r][kq*4+1]=a4.y; As[r][kq*4+2]=a4.z; As[r][kq*4+3]=a4.w; }
    { int r = idx >> 4, cq = idx & 15;
      float4 b4 = *(const float4*)(Bw + (size_t)r*Nc + col0 + cq*4);
      Bs[r][cq*4+0]=b4.x; Bs[r][cq*4+1]=b4.y; Bs[r][cq*4+2]=b4.z; Bs[r][cq*4+3]=b4.w; }
  }
  __syncthreads();
  int ty = tid >> 4, tx = tid & 15;
  float acc[4][4];
  #pragma unroll
  for (int i=0;i<4;i++){ acc[i][0]=0.f; acc[i][1]=0.f; acc[i][2]=0.f; acc[i][3]=0.f; }
  #pragma unroll
  for (int k = 0; k < 32; k++){
    float a[4], b[4];
    #pragma unroll
    for (int i=0;i<4;i++) a[i] = As[ty*4+i][k];
    #pragma unroll
    for (int j=0;j<4;j++) b[j] = Bs[k][tx*4+j];
    #pragma unroll
    for (int i=0;i<4;i++)
      #pragma unroll
      for (int j=0;j<4;j++) acc[i][j] = fmaf(a[i], b[j], acc[i][j]);
  }
  int No = (dst==0) ? 128 : 64;
  int GNo = 65*No;
  #pragma unroll
  for (int i=0;i<4;i++){
    int r = row0 + ty*4 + i;
    #pragma unroll
    for (int j=0;j<4;j++){
      int c = col0 + tx*4 + j;
      float v = acc[i][j] + g[c];
      if (dst == 2)      g_b1[(size_t)r*128 + c] = v;
      else if (dst == 3) g_bu[(size_t)r*64 + c] = v;
      else {
        int seg = c / GNo, rem = c - seg*GNo;
        int ki = rem / No, o = rem - ki*No;
        if (ki >= 1){
          size_t off = (((size_t)r*3 + seg)*64 + (ki-1))*No + o;
          if (dst == 0) g_W1f[off] = __float2half_rn(v);
          else          g_Wuf[off] = __float2half_rn(v);
        }
      }
    }
  }
}

// ---------------- 4) dual HMMA fp16: y1 = A@X, y2 = M2@X - X (3-stage, 256 thr) ----------------
constexpr int STG_SZ = 14592;
constexpr int OA = 0, OM = 6144, OX = 12288;   // bytes within stage
// static smem: 3 * 14592 = 43776 B

__global__ void __launch_bounds__(256, 2) k_bmma2(int from_yz){
  __shared__ __align__(16) char sm3[3*STG_SZ];
  uint32_t sb = s2u(sm3);
  const __half* __restrict__ Xf = from_yz ? g_yzf : g_def;
  const float* __restrict__ Z = from_yz ? g_yz : g_de;

  int bt = blockIdx.y, m0 = blockIdx.x * 128;
  int tid = threadIdx.x, wid = tid >> 5, lane = tid & 31;
  int warp_m = wid >> 1, warp_n = wid & 1;

  int arow = tid >> 1, aq = tid & 1;          // A/M2: 128 rows x 2 x 16B
  int xr = (tid & 127) >> 3, xq = tid & 7;    // X: 16 rows x 8 x 16B (threads < 128)
  bool xload = tid < 128;

  auto load_chunk = [&](int c, int st){
    uint32_t base = sb + (uint32_t)st * STG_SZ;
    int k0 = c * 16;
    size_t ga = (size_t)(m0 + arow)*512 + k0 + aq*8;
    uint32_t so = (uint32_t)arow*48 + aq*16;
    cp16(base + OA + so, g_Af + ga);
    cp16(base + OM + so, g_M2f + ga);
    if (xload){
      size_t gx = ((size_t)bt*512 + k0 + xr)*64 + xq*8;
      cp16(base + OX + (uint32_t)xr*144 + xq*16, Xf + gx);
    }
  };

  float acc1[2][4][4], acc2[2][4][4];
  #pragma unroll
  for (int mi=0;mi<2;mi++)
    #pragma unroll
    for (int nn=0;nn<4;nn++)
      #pragma unroll
      for (int j=0;j<4;j++){ acc1[mi][nn][j] = 0.f; acc2[mi][nn][j] = 0.f; }

  load_chunk(0, 0);
  asm volatile("cp.async.commit_group;" ::: "memory");
  load_chunk(1, 1);
  asm volatile("cp.async.commit_group;" ::: "memory");

  uint32_t lrow = lane & 15;
  uint32_t lk = (lane >> 4) << 4;

  for (int c = 0; c < 32; c++){
    if (c < 31) asm volatile("cp.async.wait_group 1;" ::: "memory");
    else        asm volatile("cp.async.wait_group 0;" ::: "memory");
    __syncthreads();

    int st = c % 3;
    uint32_t base = sb + (uint32_t)st * STG_SZ;
    uint32_t aoff = (uint32_t)(warp_m*32 + lrow)*48 + lk;
    uint32_t boff = lrow*144 + (uint32_t)warp_n*64 + lk;

    uint32_t bf[2][4];
    #pragma unroll
    for (int np = 0; np < 2; np++)
      ldm_x4t(bf[np], base + OX + boff + np*32);

    #pragma unroll
    for (int mi = 0; mi < 2; mi++){
      uint32_t fa[4], fm[4];
      ldm_x4(fa, base + OA + aoff + (uint32_t)mi*768);
      ldm_x4(fm, base + OM + aoff + (uint32_t)mi*768);
      #pragma unroll
      for (int nn = 0; nn < 4; nn++){
        int np = nn >> 1, sub = (nn & 1) * 2;
        mma_f16(acc1[mi][nn], fa, bf[np][sub], bf[np][sub+1]);
        mma_f16(acc2[mi][nn], fm, bf[np][sub], bf[np][sub+1]);
      }
    }
    if (c + 2 < 32){
      load_chunk(c + 2, (c + 2) % 3);
      asm volatile("cp.async.commit_group;" ::: "memory");
    }
  }

  int rbase = m0 + warp_m*32 + (lane >> 2);
  int cbase = warp_n*32 + (lane & 3)*2;
  #pragma unroll
  for (int mi = 0; mi < 2; mi++){
    #pragma unroll
    for (int nn = 0; nn < 4; nn++){
      int col = cbase + nn*8;
      #pragma unroll
      for (int half = 0; half < 2; half++){
        int row = rbase + mi*16 + half*8;
        size_t off = ((size_t)bt*512 + row)*64 + col;
        float v0 = acc1[mi][nn][half*2], v1 = acc1[mi][nn][half*2+1];
        __half2 hv; hv.x = __float2half_rn(v0); hv.y = __float2half_rn(v1);
        *(__half2*)(g_y1f + off) = hv;
        float2 z = *(const float2*)(Z + off);
        float w0 = acc2[mi][nn][half*2] - z.x;
        float w1 = acc2[mi][nn][half*2+1] - z.y;
        __half2 wv; wv.x = __float2half_rn(w0); wv.y = __float2half_rn(w1);
        *(__half2*)(g_y2f + off) = wv;
      }
    }
  }
}

// ---------------- 5) HMMA fp16 combine GEMM: act([Y0|Y1|Y2] @ W[bt] + b) ----------------
template<int WHICH>
__global__ void __launch_bounds__(256, 2) k_combT(){
  constexpr int No = WHICH ? 64 : 128;
  const __half* __restrict__ Y0f = WHICH ? g_yzf : g_def;
  const __half* __restrict__ Wf  = WHICH ? g_Wuf : g_W1f;

  __shared__ __half sA[2][128*24];
  __shared__ __half sX[2][16*72];

  int bt = blockIdx.z, n0 = blockIdx.y * 128, ct = blockIdx.x;
  int tid = threadIdx.x, wid = tid >> 5, lane = tid & 31;
  int warp_m = wid >> 1, warp_n = wid & 1;

  uint32_t uA[2] = { s2u(sA[0]), s2u(sA[1]) };
  uint32_t uX[2] = { s2u(sX[0]), s2u(sX[1]) };

  int arow = tid >> 1, aq = tid & 1;
  int xr = (tid & 127) >> 3, xq = tid & 7;
  bool xload = tid < 128;

  auto load_chunk = [&](int c, int buf){
    int seg = c >> 2, kin0 = (c & 3) * 16;
    const __half* Yf = seg==0 ? Y0f : seg==1 ? g_y1f : g_y2f;
    size_t ga = ((size_t)bt*512 + n0 + arow)*64 + kin0 + aq*8;
    cp16(uA[buf] + arow*48 + aq*16, Yf + ga);
    if (xload){
      size_t gw = (((size_t)bt*3 + seg)*64 + kin0 + xr)*No + ct*64 + xq*8;
      cp16(uX[buf] + xr*144 + xq*16, Wf + gw);
    }
  };

  float acc[2][4][4];
  #pragma unroll
  for (int mi=0;mi<2;mi++)
    #pragma unroll
    for (int nn=0;nn<4;nn++)
      #pragma unroll
      for (int j=0;j<4;j++) acc[mi][nn][j] = 0.f;

  load_chunk(0, 0);
  asm volatile("cp.async.commit_group;" ::: "memory");

  uint32_t lrow = lane & 15;
  uint32_t lk = (lane >> 4) << 4;

  for (int c = 0; c < 12; c++){
    int buf = c & 1;
    if (c < 11){
      load_chunk(c + 1, buf ^ 1);
      asm volatile("cp.async.commit_group;" ::: "memory");
      asm volatile("cp.async.wait_group 1;" ::: "memory");
    } else {
      asm volatile("cp.async.wait_group 0;" ::: "memory");
    }
    __syncthreads();

    uint32_t af[2][4], bf[2][4];
    #pragma unroll
    for (int mi = 0; mi < 2; mi++)
      ldm_x4(af[mi], uA[buf] + (uint32_t)(warp_m*32 + mi*16 + lrow)*48 + lk);
    #pragma unroll
    for (int np = 0; np < 2; np++)
      ldm_x4t(bf[np], uX[buf] + lrow*144 + (uint32_t)(warp_n*32 + np*16)*2 + lk);
    #pragma unroll
    for (int mi = 0; mi < 2; mi++){
      #pragma unroll
      for (int nn = 0; nn < 4; nn++){
        int np = nn >> 1, sub = (nn & 1) * 2;
        mma_f16(acc[mi][nn], af[mi], bf[np][sub], bf[np][sub+1]);
      }
    }
    __syncthreads();
  }

  int rbase = n0 + warp_m*32 + (lane >> 2);
  int cbase = warp_n*32 + (lane & 3)*2;
  #pragma unroll
  for (int mi = 0; mi < 2; mi++){
    #pragma unroll
    for (int nn = 0; nn < 4; nn++){
      int col = cbase + nn*8;
      int gcol = ct*64 + col;
      #pragma unroll
      for (int half = 0; half < 2; half++){
        int row = rbase + mi*16 + half*8;
        size_t off = ((size_t)bt*512 + row)*64 + col;
        float v0 = acc[mi][nn][half*2], v1 = acc[mi][nn][half*2+1];
        if (WHICH == 0){
          v0 += g_b1[(size_t)bt*128 + gcol];
          v1 += g_b1[(size_t)bt*128 + gcol + 1];
          v0 = 1.f/(1.f + __expf(-v0));
          v1 = 1.f/(1.f + __expf(-v1));
          if (ct == 0){
            float2 de = *(const float2*)(g_de + off);
            float z0 = v0 * de.x, z1 = v1 * de.y;
            *(float2*)(g_yz + off) = make_float2(z0, z1);
            __half2 hv; hv.x = __float2half_rn(z0); hv.y = __float2half_rn(z1);
            *(__half2*)(g_yzf + off) = hv;
          } else {
            *(float2*)(g_rg + off) = make_float2(v0, v1);
          }
        } else {
          v0 = tanhf(v0 + g_bu[(size_t)bt*64 + gcol]);
          v1 = tanhf(v1 + g_bu[(size_t)bt*64 + gcol + 1]);
          *(float2*)(g_hc + off) = make_float2(v0, v1);
        }
      }
    }
  }
}

// ---------------- 6) final projection ----------------
__global__ void k_out(const float* __restrict__ outw, const float* __restrict__ outb,
                      float* __restrict__ out){
  int gw = blockIdx.x*8 + (threadIdx.x >> 5);
  int lane = threadIdx.x & 31;
  size_t mn = (size_t)gw;
  int m = gw >> 9;
  int t = m % 12;
  size_t base = mn << 6;
  float s = 0.f;
  #pragma unroll
  for (int ii = 0; ii < 2; ii++){
    int i = lane + ii*32;
    float rg = g_rg[base + i];
    float de = g_de[base + i];
    float hc = g_hc[base + i];
    float st = fmaf(rg, de - hc, hc);
    s = fmaf(st, outw[t*64 + i], s);
  }
  #pragma unroll
  for (int off = 16; off > 0; off >>= 1) s += __shfl_xor_sync(0xffffffffu, s, off);
  if (lane == 0) out[mn] = s + outb[t];
}

// ---------------- launch ----------------
extern "C" void kernel_launch(void* const* d_in, const int* in_sizes, int n_in,
                              void* d_out, int out_size){
  (void)in_sizes; (void)n_in; (void)out_size;
  const float* hn  = (const float*)d_in[2];
  const float* ne1 = (const float*)d_in[3];
  const float* ne2 = (const float*)d_in[4];
  const float* E   = (const float*)d_in[5];
  const float* Wq  = (const float*)d_in[6];
  const float* bq  = (const float*)d_in[7];
  const float* Wk  = (const float*)d_in[8];
  const float* bk  = (const float*)d_in[9];
  const float* Wv  = (const float*)d_in[10];
  const float* bv  = (const float*)d_in[11];
  const float* taw = (const float*)d_in[12];
  const float* tab = (const float*)d_in[13];
  const float* gwp = (const float*)d_in[14];
  const float* gw  = (const float*)d_in[15];
  const float* gbp = (const float*)d_in[16];
  const float* gb  = (const float*)d_in[17];
  const float* uwp = (const float*)d_in[18];
  const float* uw  = (const float*)d_in[19];
  const float* ubp = (const float*)d_in[20];
  const float* ub  = (const float*)d_in[21];
  const float* outw= (const float*)d_in[22];
  const float* outb= (const float*)d_in[23];
  float* out = (float*)d_out;

  cudaFuncSetAttribute(k_qa, cudaFuncAttributeMaxDynamicSharedMemorySize, QA_SMB);

  k_adj<<<512, 512>>>(E);
  k_a2<<<dim3(4, 8), 128>>>();
  k_qa<<<512, 256, QA_SMB>>>(hn, ne1, ne2, Wq, bq, Wk, bk, Wv, bv, taw, tab);
  k_bmma2<<<dim3(4, 768), 256>>>(0);             // 4 (profiled)
  k_wgen<<<dim3(390, 12), 256>>>(ne2, gwp, gw, 24960, 0);
  k_wgen<<<dim3(195, 12), 256>>>(ne2, uwp, uw, 12480, 1);
  k_wgen<<<dim3(2, 12), 256>>>(ne2, gbp, gb, 128, 2);
  k_wgen<<<dim3(1, 12), 256>>>(ne2, ubp, ub, 64, 3);
  k_combT<0><<<dim3(2, 4, 768), 256>>>();        // yz / rg
  k_bmma2<<<dim3(4, 768), 256>>>(1);
  k_combT<1><<<dim3(1, 4, 768), 256>>>();        // hc
  k_out<<<49152, 256>>>(outw, outb, out);
}

// round 11
// speedup vs baseline: 2.0548x; 1.1472x over previous
#include <cuda_runtime.h>
#include <cuda_fp16.h>
#include <math.h>
#include <stdint.h>

// B=64, T=12, N=512, H=64, TD=32, ED=16, CHEB_K=3, D_HEADS=8, M=768
constexpr size_t NF = (size_t)768*512*64;

// ---------------- device scratch ----------------
__device__ float g_Af32[512*512];
__device__ __half g_Af[512*512], g_M2f[512*512];
__device__ float g_de[NF], g_yz[NF], g_rg[NF];
__device__ __half g_def[NF], g_y1f[NF], g_y2f[NF], g_yzf[NF];
__device__ __half g_W1f[(size_t)768*3*64*128];
__device__ __half g_Wuf[(size_t)768*3*64*64];
__device__ float g_b1[768*128], g_bu[768*64];

// ---------------- ptx helpers (sm_80+ baseline only) ----------------
__device__ __forceinline__ uint32_t s2u(const void* p){
  uint32_t a;
  asm("{ .reg .u64 t; cvta.to.shared.u64 t, %1; cvt.u32.u64 %0, t; }" : "=r"(a) : "l"(p));
  return a;
}
__device__ __forceinline__ void cp16(uint32_t dst, const void* src){
  asm volatile("cp.async.cg.shared.global [%0], [%1], 16;" :: "r"(dst), "l"(src) : "memory");
}
__device__ __forceinline__ void ldm_x4(uint32_t* r, uint32_t addr){
  asm volatile("ldmatrix.sync.aligned.m8n8.x4.shared.b16 {%0,%1,%2,%3}, [%4];"
    : "=r"(r[0]), "=r"(r[1]), "=r"(r[2]), "=r"(r[3]) : "r"(addr));
}
__device__ __forceinline__ void ldm_x4t(uint32_t* r, uint32_t addr){
  asm volatile("ldmatrix.sync.aligned.m8n8.x4.trans.shared.b16 {%0,%1,%2,%3}, [%4];"
    : "=r"(r[0]), "=r"(r[1]), "=r"(r[2]), "=r"(r[3]) : "r"(addr));
}
__device__ __forceinline__ void mma_f16(float* c, const uint32_t* a, uint32_t b0, uint32_t b1){
  asm volatile(
    "mma.sync.aligned.m16n8k16.row.col.f32.f16.f16.f32 "
    "{%0,%1,%2,%3}, {%4,%5,%6,%7}, {%8,%9}, {%0,%1,%2,%3};"
    : "+f"(c[0]), "+f"(c[1]), "+f"(c[2]), "+f"(c[3])
    : "r"(a[0]), "r"(a[1]), "r"(a[2]), "r"(a[3]), "r"(b0), "r"(b1));
}

// ---------------- 1) adjacency (fp32 + fp16) ----------------
__global__ void k_adj(const float* __restrict__ E){
  int i = blockIdx.x, j = threadIdx.x;
  __shared__ float Ei[16];
  __shared__ float red[512];
  if (j < 16) Ei[j] = E[i*16 + j];
  __syncthreads();
  float d = 0.f;
  #pragma unroll
  for (int c = 0; c < 16; c++) d = fmaf(Ei[c], E[j*16 + c], d);
  d = fmaxf(d, 0.f);
  red[j] = d; __syncthreads();
  for (int s = 256; s > 0; s >>= 1){ if (j < s) red[j] = fmaxf(red[j], red[j+s]); __syncthreads(); }
  float mx = red[0];
  __syncthreads();
  float e = __expf(d - mx);
  red[j] = e; __syncthreads();
  for (int s = 256; s > 0; s >>= 1){ if (j < s) red[j] += red[j+s]; __syncthreads(); }
  float a = e * (1.f / red[0]);
  g_Af32[i*512 + j] = a;
  g_Af[i*512 + j] = __float2half_rn(a);
}

// ---------------- 1b) M2 = 2*A@A -> fp16 ----------------
__global__ void k_a2(){
  int row0 = blockIdx.x * 128, col0 = blockIdx.y * 64;
  __shared__ float As[128][17];
  __shared__ __align__(16) float Bs[16][64];
  int tid = threadIdx.x;
  int tx = tid & 7, ty = tid >> 3;
  float acc[8][8];
  #pragma unroll
  for (int i=0;i<8;i++)
    #pragma unroll
    for (int j=0;j<8;j++) acc[i][j] = 0.f;
  for (int k0 = 0; k0 < 512; k0 += 16){
    #pragma unroll
    for (int i = 0; i < 4; i++){
      int idx = tid + i*128;
      int r = idx >> 2, kq = idx & 3;
      float4 a4 = *(const float4*)(g_Af32 + (size_t)(row0 + r)*512 + k0 + kq*4);
      As[r][kq*4+0]=a4.x; As[r][kq*4+1]=a4.y; As[r][kq*4+2]=a4.z; As[r][kq*4+3]=a4.w;
    }
    #pragma unroll
    for (int i = 0; i < 2; i++){
      int idx = tid + i*128;
      int r = idx >> 4, cq = idx & 15;
      float4 b4 = *(const float4*)(g_Af32 + (size_t)(k0 + r)*512 + col0 + cq*4);
      *(float4*)&Bs[r][cq*4] = b4;
    }
    __syncthreads();
    #pragma unroll
    for (int k = 0; k < 16; k++){
      float a[8], b[8];
      #pragma unroll
      for (int i=0;i<8;i++) a[i] = As[ty*8+i][k];
      float4 b0 = *(const float4*)&Bs[k][tx*8];
      float4 b1 = *(const float4*)&Bs[k][tx*8+4];
      b[0]=b0.x; b[1]=b0.y; b[2]=b0.z; b[3]=b0.w;
      b[4]=b1.x; b[5]=b1.y; b[6]=b1.z; b[7]=b1.w;
      #pragma unroll
      for (int i=0;i<8;i++)
        #pragma unroll
        for (int j=0;j<8;j++) acc[i][j] = fmaf(a[i], b[j], acc[i][j]);
    }
    __syncthreads();
  }
  #pragma unroll
  for (int i=0;i<8;i++){
    size_t r = row0 + ty*8 + i;
    #pragma unroll
    for (int j=0;j<8;j++)
      g_M2f[r*512 + col0 + tx*8 + j] = __float2half_rn(2.f * acc[i][j]);
  }
}

// ---------------- 2) fused prep + qkvu + attention -> de (fp32 + fp16) ----------------
constexpr int QA_OX  = 0;
constexpr int QA_OB  = 4352;
constexpr int QA_OQ  = 8704;
constexpr int QA_OPQ = 25344;
constexpr int QA_OPK = 26112;
constexpr int QA_OPV = 26176;
constexpr int QA_OES = 26240;
constexpr int QA_SMB = 27008 * 4;

__global__ void __launch_bounds__(256, 2) k_qa(
    const float* __restrict__ hn, const float* __restrict__ ne1, const float* __restrict__ ne2,
    const float* __restrict__ Wq, const float* __restrict__ bq,
    const float* __restrict__ Wk, const float* __restrict__ bk,
    const float* __restrict__ Wv, const float* __restrict__ bv,
    const float* __restrict__ taw, const float* __restrict__ tab){
  extern __shared__ float sm[];
  float* Xs = sm + QA_OX;
  float* Bs = sm + QA_OB;
  float* Q  = sm + QA_OQ;
  float* pq = sm + QA_OPQ;
  float* pk = sm + QA_OPK;
  float* pv = sm + QA_OPV;
  float* es = sm + QA_OES;
  int tid = threadIdx.x;
  int bn0 = blockIdx.x * 64;
  int b = bn0 >> 9;

  #pragma unroll
  for (int i = tid; i < 64*16; i += 256){
    int r = i >> 4, q = i & 15;
    float4 v = *(const float4*)(hn + (size_t)(bn0 + r)*64 + q*4);
    Xs[r*68 + q*4+0]=v.x; Xs[r*68 + q*4+1]=v.y; Xs[r*68 + q*4+2]=v.z; Xs[r*68 + q*4+3]=v.w;
  }
  const float* e1 = ne1 + (size_t)(b*12 + 11)*32;
  if (tid < 64){
    float a = bk[tid];
    #pragma unroll
    for (int d = 0; d < 32; d++) a = fmaf(e1[d], Wk[d*64 + tid], a);
    pk[tid] = a;
  } else if (tid < 128){
    int o = tid - 64;
    float a = bv[o];
    #pragma unroll
    for (int d = 0; d < 32; d++) a = fmaf(e1[d], Wv[d*64 + o], a);
    pv[o] = a;
  }
  for (int i = tid; i < 768; i += 256){
    int t = i >> 6, o = i & 63;
    const float* e2 = ne2 + (size_t)(b*12 + t)*32;
    float a = bq[o];
    #pragma unroll
    for (int d = 0; d < 32; d++) a = fmaf(e2[d], Wq[d*64 + o], a);
    pq[t*64 + o] = a;
  }
  __syncthreads();

  int ty = tid >> 4, tx = tid & 15;
  for (int mode = 0; mode < 4; mode++){
    const float* Wsrc = (mode==0) ? Wq + 2048 : (mode==1) ? Wk + 2048
                      : (mode==2) ? Wv + 2048 : taw;
    #pragma unroll
    for (int i = tid; i < 64*16; i += 256){
      int r = i >> 4, q = i & 15;
      float4 w4 = *(const float4*)(Wsrc + (size_t)r*64 + q*4);
      Bs[r*68 + q*4+0]=w4.x; Bs[r*68 + q*4+1]=w4.y; Bs[r*68 + q*4+2]=w4.z; Bs[r*68 + q*4+3]=w4.w;
    }
    __syncthreads();
    float acc[4][4];
    #pragma unroll
    for (int i=0;i<4;i++){ acc[i][0]=0.f; acc[i][1]=0.f; acc[i][2]=0.f; acc[i][3]=0.f; }
    #pragma unroll 16
    for (int k = 0; k < 64; k++){
      float a[4], bb[4];
      #pragma unroll
      for (int i=0;i<4;i++) a[i] = Xs[(ty*4+i)*68 + k];
      #pragma unroll
      for (int j=0;j<4;j++) bb[j] = Bs[k*68 + tx*4+j];
      #pragma unroll
      for (int i=0;i<4;i++)
        #pragma unroll
        for (int j=0;j<4;j++) acc[i][j] = fmaf(a[i], bb[j], acc[i][j]);
    }
    #pragma unroll
    for (int i=0;i<4;i++){
      int r = ty*4 + i;
      #pragma unroll
      for (int j=0;j<4;j++){
        int c = tx*4 + j;
        float v = acc[i][j];
        if (mode == 1)      v = fmaxf(v + pk[c], 0.f);
        else if (mode == 2) v = fmaxf(v + pv[c], 0.f);
        else if (mode == 3) v = v + tab[c];
        Q[r*260 + mode*64 + c] = v;
      }
    }
    __syncthreads();
  }
  for (int i = tid; i < 4096; i += 256) Bs[(i>>6)*68 + (i&63)] = taw[4096 + i];
  __syncthreads();

  int w = tid >> 5, lane = tid & 31;
  float* esw = es + w*96;
  int c0 = lane*2;
  for (int i = 0; i < 8; i++){
    int lr = w*8 + i;
    int n = (bn0 + lr) & 511;
    const float* q_ = Q + lr*260;
    float u0 = q_[192+c0], u1 = q_[193+c0];
    float vw0[8], vw1[8];
    #pragma unroll
    for (int d = 0; d < 8; d++){
      float a0 = 0.f, a1 = 0.f;
      #pragma unroll
      for (int cp = 0; cp < 8; cp++){
        float vv = q_[128 + d*8 + cp];
        float2 t2 = *(const float2*)&Bs[(d*8+cp)*68 + c0];
        a0 = fmaf(vv, t2.x, a0); a1 = fmaf(vv, t2.y, a1);
      }
      vw0[d] = a0; vw1[d] = a1;
    }
    for (int task = lane; task < 96; task += 32){
      int d = task / 12, t = task - d*12;
      const float* pqd = pq + t*64 + d*8;
      float e = 0.f;
      #pragma unroll
      for (int cp = 0; cp < 8; cp++){
        float qv = fmaxf(q_[d*8+cp] + pqd[cp], 0.f);
        e = fmaf(qv, q_[64 + d*8 + cp], e);
      }
      esw[d*12 + t] = e;
    }
    __syncwarp();
    if (lane < 8){
      float mx = -1e30f;
      #pragma unroll
      for (int t=0;t<12;t++) mx = fmaxf(mx, esw[lane*12 + t]);
      float ssum = 0.f;
      #pragma unroll
      for (int t=0;t<12;t++){ float ex = __expf(esw[lane*12+t]-mx); esw[lane*12+t]=ex; ssum+=ex; }
      float inv = 1.f/ssum;
      #pragma unroll
      for (int t=0;t<12;t++) esw[lane*12+t] *= inv;
    }
    __syncwarp();
    #pragma unroll
    for (int t = 0; t < 12; t++){
      float o0 = u0, o1 = u1;
      #pragma unroll
      for (int d = 0; d < 8; d++){
        float a = esw[d*12 + t];
        o0 = fmaf(a, vw0[d], o0); o1 = fmaf(a, vw1[d], o1);
      }
      size_t off = ((size_t)(b*12 + t)*512 + n)*64;
      *(float2*)(g_de + off + c0) = make_float2(o0, o1);
      __half2 hv; hv.x = __float2half_rn(o0); hv.y = __float2half_rn(o1);
      *(__half2*)(g_def + off + c0) = hv;
    }
    __syncwarp();
  }
}

// ---------------- 3) weight gen -> fp16 W (dead row-0 dropped) + fp32 biases ----------------
__global__ void k_wgen(const float* __restrict__ Am, const float* __restrict__ Bw,
                       const float* __restrict__ g, int Nc, int dst){
  int col0 = blockIdx.x * 64, row0 = blockIdx.y * 64;
  __shared__ float As[64][33];
  __shared__ float Bs[32][65];
  int tid = threadIdx.x;
  #pragma unroll
  for (int i = 0; i < 2; i++){
    int idx = tid + i*256;
    { int r = idx >> 3, kq = idx & 7;
      float4 a4 = *(const float4*)(Am + (size_t)(row0 + r)*32 + kq*4);
      As[r][kq*4+0]=a4.x; As[r][kq*4+1]=a4.y; As[r][kq*4+2]=a4.z; As[r][kq*4+3]=a4.w; }
    { int r = idx >> 4, cq = idx & 15;
      float4 b4 = *(const float4*)(Bw + (size_t)r*Nc + col0 + cq*4);
      Bs[r][cq*4+0]=b4.x; Bs[r][cq*4+1]=b4.y; Bs[r][cq*4+2]=b4.z; Bs[r][cq*4+3]=b4.w; }
  }
  __syncthreads();
  int ty = tid >> 4, tx = tid & 15;
  float acc[4][4];
  #pragma unroll
  for (int i=0;i<4;i++){ acc[i][0]=0.f; acc[i][1]=0.f; acc[i][2]=0.f; acc[i][3]=0.f; }
  #pragma unroll
  for (int k = 0; k < 32; k++){
    float a[4], b[4];
    #pragma unroll
    for (int i=0;i<4;i++) a[i] = As[ty*4+i][k];
    #pragma unroll
    for (int j=0;j<4;j++) b[j] = Bs[k][tx*4+j];
    #pragma unroll
    for (int i=0;i<4;i++)
      #pragma unroll
      for (int j=0;j<4;j++) acc[i][j] = fmaf(a[i], b[j], acc[i][j]);
  }
  int No = (dst==0) ? 128 : 64;
  int GNo = 65*No;
  #pragma unroll
  for (int i=0;i<4;i++){
    int r = row0 + ty*4 + i;
    #pragma unroll
    for (int j=0;j<4;j++){
      int c = col0 + tx*4 + j;
      float v = acc[i][j] + g[c];
      if (dst == 2)      g_b1[(size_t)r*128 + c] = v;
      else if (dst == 3) g_bu[(size_t)r*64 + c] = v;
      else {
        int seg = c / GNo, rem = c - seg*GNo;
        int ki = rem / No, o = rem - ki*No;
        if (ki >= 1){
          size_t off = (((size_t)r*3 + seg)*64 + (ki-1))*No + o;
          if (dst == 0) g_W1f[off] = __float2half_rn(v);
          else          g_Wuf[off] = __float2half_rn(v);
        }
      }
    }
  }
}

// ---------------- 4) dual HMMA fp16: y1 = A@X, y2 = M2@X - X (BK=32, 16 chunks, 3-stage) ----------------
constexpr int STG_SZ = 25088;
constexpr int OA = 0;         // A: 128 rows x 80B = 10240
constexpr int OM = 10240;     // M2: same
constexpr int OX = 20480;     // X: 32 rows x 144B = 4608
constexpr int SMB = 3 * STG_SZ;   // 75264

__global__ void __launch_bounds__(256, 2) k_bmma2(int from_yz){
  extern __shared__ __align__(16) char dynsm[];
  uint32_t sb = s2u(dynsm);
  const __half* __restrict__ Xf = from_yz ? g_yzf : g_def;
  const float* __restrict__ Z = from_yz ? g_yz : g_de;

  int bt = blockIdx.y, m0 = blockIdx.x * 128;
  int tid = threadIdx.x, wid = tid >> 5, lane = tid & 31;
  int warp_m = wid >> 1, warp_n = wid & 1;

  int arow = tid >> 2, aq = tid & 3;          // A/M2: 128 rows x 4 x 16B (2 rows/thread)
  int xr = (tid & 255) >> 3, xq = tid & 7;    // X: 32 rows x 8 x 16B

  auto load_chunk = [&](int c, int st){
    uint32_t base = sb + (uint32_t)st * STG_SZ;
    int k0 = c * 32;
    #pragma unroll
    for (int rr = 0; rr < 128; rr += 64){
      int row = arow + rr;
      size_t ga = (size_t)(m0 + row)*512 + k0 + aq*8;
      uint32_t so = (uint32_t)row*80 + aq*16;
      cp16(base + OA + so, g_Af + ga);
      cp16(base + OM + so, g_M2f + ga);
    }
    size_t gx = ((size_t)bt*512 + k0 + xr)*64 + xq*8;
    cp16(base + OX + (uint32_t)xr*144 + xq*16, Xf + gx);
  };

  float acc1[2][4][4], acc2[2][4][4];
  #pragma unroll
  for (int mi=0;mi<2;mi++)
    #pragma unroll
    for (int nn=0;nn<4;nn++)
      #pragma unroll
      for (int j=0;j<4;j++){ acc1[mi][nn][j] = 0.f; acc2[mi][nn][j] = 0.f; }

  load_chunk(0, 0);
  asm volatile("cp.async.commit_group;" ::: "memory");
  load_chunk(1, 1);
  asm volatile("cp.async.commit_group;" ::: "memory");

  uint32_t lrow = lane & 15;
  uint32_t lk = (lane >> 4) << 4;

  for (int c = 0; c < 16; c++){
    if (c < 15) asm volatile("cp.async.wait_group 1;" ::: "memory");
    else        asm volatile("cp.async.wait_group 0;" ::: "memory");
    __syncthreads();

    int st = c % 3;
    uint32_t base = sb + (uint32_t)st * STG_SZ;
    #pragma unroll
    for (int kh = 0; kh < 2; kh++){
      uint32_t bf[2][4];
      uint32_t boff = (uint32_t)kh*2304 + lrow*144 + (uint32_t)warp_n*64 + lk;
      #pragma unroll
      for (int np = 0; np < 2; np++)
        ldm_x4t(bf[np], base + OX + boff + np*32);
      #pragma unroll
      for (int mi = 0; mi < 2; mi++){
        uint32_t aoff = (uint32_t)(warp_m*32 + mi*16 + lrow)*80 + kh*32 + lk;
        uint32_t fa[4], fm[4];
        ldm_x4(fa, base + OA + aoff);
        ldm_x4(fm, base + OM + aoff);
        #pragma unroll
        for (int nn = 0; nn < 4; nn++){
          int np = nn >> 1, sub = (nn & 1) * 2;
          mma_f16(acc1[mi][nn], fa, bf[np][sub], bf[np][sub+1]);
          mma_f16(acc2[mi][nn], fm, bf[np][sub], bf[np][sub+1]);
        }
      }
    }
    if (c + 2 < 16){
      load_chunk(c + 2, (c + 2) % 3);
      asm volatile("cp.async.commit_group;" ::: "memory");
    }
  }

  int rbase = m0 + warp_m*32 + (lane >> 2);
  int cbase = warp_n*32 + (lane & 3)*2;
  #pragma unroll
  for (int mi = 0; mi < 2; mi++){
    #pragma unroll
    for (int nn = 0; nn < 4; nn++){
      int col = cbase + nn*8;
      #pragma unroll
      for (int half = 0; half < 2; half++){
        int row = rbase + mi*16 + half*8;
        size_t off = ((size_t)bt*512 + row)*64 + col;
        float v0 = acc1[mi][nn][half*2], v1 = acc1[mi][nn][half*2+1];
        __half2 hv; hv.x = __float2half_rn(v0); hv.y = __float2half_rn(v1);
        *(__half2*)(g_y1f + off) = hv;
        float2 z = *(const float2*)(Z + off);
        float w0 = acc2[mi][nn][half*2] - z.x;
        float w1 = acc2[mi][nn][half*2+1] - z.y;
        __half2 wv; wv.x = __float2half_rn(w0); wv.y = __float2half_rn(w1);
        *(__half2*)(g_y2f + off) = wv;
      }
    }
  }
}

// ---------------- 5) HMMA fp16 combine (3-stage 1-sync; WHICH=1 fuses final projection) ----------------
template<int WHICH>
__global__ void __launch_bounds__(256, 2) k_combT(const float* __restrict__ outw,
                                                  const float* __restrict__ outb,
                                                  float* __restrict__ out){
  constexpr int No = WHICH ? 64 : 128;
  const __half* __restrict__ Y0f = WHICH ? g_yzf : g_def;
  const __half* __restrict__ Wf  = WHICH ? g_Wuf : g_W1f;

  __shared__ __half sA[3][128*24];
  __shared__ __half sX[3][16*72];
  __shared__ float spart[128][2];

  int bt = blockIdx.z, n0 = blockIdx.y * 128, ct = blockIdx.x;
  int tid = threadIdx.x, wid = tid >> 5, lane = tid & 31;
  int warp_m = wid >> 1, warp_n = wid & 1;

  uint32_t uA[3] = { s2u(sA[0]), s2u(sA[1]), s2u(sA[2]) };
  uint32_t uX[3] = { s2u(sX[0]), s2u(sX[1]), s2u(sX[2]) };

  int arow = tid >> 1, aq = tid & 1;
  int xr = (tid & 127) >> 3, xq = tid & 7;
  bool xload = tid < 128;

  auto load_chunk = [&](int c, int st){
    int seg = c >> 2, kin0 = (c & 3) * 16;
    const __half* Yf = seg==0 ? Y0f : seg==1 ? g_y1f : g_y2f;
    size_t ga = ((size_t)bt*512 + n0 + arow)*64 + kin0 + aq*8;
    cp16(uA[st] + arow*48 + aq*16, Yf + ga);
    if (xload){
      size_t gw = (((size_t)bt*3 + seg)*64 + kin0 + xr)*No + ct*64 + xq*8;
      cp16(uX[st] + xr*144 + xq*16, Wf + gw);
    }
  };

  float acc[2][4][4];
  #pragma unroll
  for (int mi=0;mi<2;mi++)
    #pragma unroll
    for (int nn=0;nn<4;nn++)
      #pragma unroll
      for (int j=0;j<4;j++) acc[mi][nn][j] = 0.f;

  load_chunk(0, 0);
  asm volatile("cp.async.commit_group;" ::: "memory");
  load_chunk(1, 1);
  asm volatile("cp.async.commit_group;" ::: "memory");

  uint32_t lrow = lane & 15;
  uint32_t lk = (lane >> 4) << 4;

  for (int c = 0; c < 12; c++){
    if (c < 11) asm volatile("cp.async.wait_group 1;" ::: "memory");
    else        asm volatile("cp.async.wait_group 0;" ::: "memory");
    __syncthreads();

    int st = c % 3;
    uint32_t af[2][4], bf[2][4];
    #pragma unroll
    for (int mi = 0; mi < 2; mi++)
      ldm_x4(af[mi], uA[st] + (uint32_t)(warp_m*32 + mi*16 + lrow)*48 + lk);
    #pragma unroll
    for (int np = 0; np < 2; np++)
      ldm_x4t(bf[np], uX[st] + lrow*144 + (uint32_t)(warp_n*32 + np*16)*2 + lk);
    #pragma unroll
    for (int mi = 0; mi < 2; mi++){
      #pragma unroll
      for (int nn = 0; nn < 4; nn++){
        int np = nn >> 1, sub = (nn & 1) * 2;
        mma_f16(acc[mi][nn], af[mi], bf[np][sub], bf[np][sub+1]);
      }
    }
    if (c + 2 < 12){
      load_chunk(c + 2, (c + 2) % 3);
      asm volatile("cp.async.commit_group;" ::: "memory");
    }
  }

  int rbase = n0 + warp_m*32 + (lane >> 2);
  int cbase = warp_n*32 + (lane & 3)*2;
  int t = bt % 12;
  float part[2][2] = {{0.f,0.f},{0.f,0.f}};
  #pragma unroll
  for (int mi = 0; mi < 2; mi++){
    #pragma unroll
    for (int nn = 0; nn < 4; nn++){
      int col = cbase + nn*8;
      int gcol = ct*64 + col;
      #pragma unroll
      for (int half = 0; half < 2; half++){
        int row = rbase + mi*16 + half*8;
        size_t off = ((size_t)bt*512 + row)*64 + col;
        float v0 = acc[mi][nn][half*2], v1 = acc[mi][nn][half*2+1];
        if (WHICH == 0){
          v0 += g_b1[(size_t)bt*128 + gcol];
          v1 += g_b1[(size_t)bt*128 + gcol + 1];
          v0 = 1.f/(1.f + __expf(-v0));
          v1 = 1.f/(1.f + __expf(-v1));
          if (ct == 0){
            float2 de = *(const float2*)(g_de + off);
            float z0 = v0 * de.x, z1 = v1 * de.y;
            *(float2*)(g_yz + off) = make_float2(z0, z1);
            __half2 hv; hv.x = __float2half_rn(z0); hv.y = __float2half_rn(z1);
            *(__half2*)(g_yzf + off) = hv;
          } else {
            *(float2*)(g_rg + off) = make_float2(v0, v1);
          }
        } else {
          // hc = tanh(v + bu); st = rg*de + (1-rg)*hc; accumulate st·out_w
          float h0 = tanhf(v0 + g_bu[(size_t)bt*64 + gcol]);
          float h1 = tanhf(v1 + g_bu[(size_t)bt*64 + gcol + 1]);
          float2 rg2 = *(const float2*)(g_rg + off);
          float2 de2 = *(const float2*)(g_de + off);
          float st0 = fmaf(rg2.x, de2.x - h0, h0);
          float st1 = fmaf(rg2.y, de2.y - h1, h1);
          part[mi][half] += st0 * outw[t*64 + gcol] + st1 * outw[t*64 + gcol + 1];
        }
      }
    }
  }
  if (WHICH == 1){
    // reduce over the 4 lanes sharing a row, then across warp_n via smem
    #pragma unroll
    for (int mi = 0; mi < 2; mi++)
      #pragma unroll
      for (int half = 0; half < 2; half++){
        float p = part[mi][half];
        p += __shfl_xor_sync(0xffffffffu, p, 1);
        p += __shfl_xor_sync(0xffffffffu, p, 2);
        if ((lane & 3) == 0){
          int rl = warp_m*32 + mi*16 + half*8 + (lane >> 2);
          spart[rl][warp_n] = p;
        }
      }
    __syncthreads();
    if (tid < 128)
      out[(size_t)bt*512 + n0 + tid] = spart[tid][0] + spart[tid][1] + outb[t];
  }
}

// ---------------- launch ----------------
extern "C" void kernel_launch(void* const* d_in, const int* in_sizes, int n_in,
                              void* d_out, int out_size){
  (void)in_sizes; (void)n_in; (void)out_size;
  const float* hn  = (const float*)d_in[2];
  const float* ne1 = (const float*)d_in[3];
  const float* ne2 = (const float*)d_in[4];
  const float* E   = (const float*)d_in[5];
  const float* Wq  = (const float*)d_in[6];
  const float* bq  = (const float*)d_in[7];
  const float* Wk  = (const float*)d_in[8];
  const float* bk  = (const float*)d_in[9];
  const float* Wv  = (const float*)d_in[10];
  const float* bv  = (const float*)d_in[11];
  const float* taw = (const float*)d_in[12];
  const float* tab = (const float*)d_in[13];
  const float* gwp = (const float*)d_in[14];
  const float* gw  = (const float*)d_in[15];
  const float* gbp = (const float*)d_in[16];
  const float* gb  = (const float*)d_in[17];
  const float* uwp = (const float*)d_in[18];
  const float* uw  = (const float*)d_in[19];
  const float* ubp = (const float*)d_in[20];
  const float* ub  = (const float*)d_in[21];
  const float* outw= (const float*)d_in[22];
  const float* outb= (const float*)d_in[23];
  float* out = (float*)d_out;

  cudaFuncSetAttribute(k_qa, cudaFuncAttributeMaxDynamicSharedMemorySize, QA_SMB);
  cudaFuncSetAttribute(k_bmma2, cudaFuncAttributeMaxDynamicSharedMemorySize, SMB);

  k_adj<<<512, 512>>>(E);
  k_a2<<<dim3(4, 8), 128>>>();
  k_qa<<<512, 256, QA_SMB>>>(hn, ne1, ne2, Wq, bq, Wk, bk, Wv, bv, taw, tab);
  k_bmma2<<<dim3(4, 768), 256, SMB>>>(0);        // (profiled slot)
  k_wgen<<<dim3(390, 12), 256>>>(ne2, gwp, gw, 24960, 0);
  k_wgen<<<dim3(195, 12), 256>>>(ne2, uwp, uw, 12480, 1);
  k_wgen<<<dim3(2, 12), 256>>>(ne2, gbp, gb, 128, 2);
  k_wgen<<<dim3(1, 12), 256>>>(ne2, ubp, ub, 64, 3);
  k_combT<0><<<dim3(2, 4, 768), 256>>>(nullptr, nullptr, nullptr);   // yz / rg
  k_bmma2<<<dim3(4, 768), 256, SMB>>>(1);
  k_combT<1><<<dim3(1, 4, 768), 256>>>(outw, outb, out);             // hc + final proj
}

// round 12
// speedup vs baseline: 2.0695x; 1.0072x over previous
#include <cuda_runtime.h>
#include <cuda_fp16.h>
#include <math.h>
#include <stdint.h>

// B=64, T=12, N=512, H=64, TD=32, ED=16, CHEB_K=3, D_HEADS=8, M=768
constexpr size_t NF = (size_t)768*512*64;

// ---------------- device scratch ----------------
__device__ float g_Af32[512*512];
__device__ __half g_Af[512*512], g_M2f[512*512];
__device__ float g_de[NF], g_rg[NF];
__device__ __half g_def[NF], g_y1f[NF], g_y2f[NF], g_yzf[NF];
__device__ __half g_W1f[(size_t)768*3*64*128];
__device__ __half g_Wuf[(size_t)768*3*64*64];
__device__ float g_b1[768*128], g_bu[768*64];

// ---------------- ptx helpers (sm_80+ baseline only) ----------------
__device__ __forceinline__ uint32_t s2u(const void* p){
  uint32_t a;
  asm("{ .reg .u64 t; cvta.to.shared.u64 t, %1; cvt.u32.u64 %0, t; }" : "=r"(a) : "l"(p));
  return a;
}
__device__ __forceinline__ void cp16(uint32_t dst, const void* src){
  asm volatile("cp.async.cg.shared.global [%0], [%1], 16;" :: "r"(dst), "l"(src) : "memory");
}
__device__ __forceinline__ void ldm_x4(uint32_t* r, uint32_t addr){
  asm volatile("ldmatrix.sync.aligned.m8n8.x4.shared.b16 {%0,%1,%2,%3}, [%4];"
    : "=r"(r[0]), "=r"(r[1]), "=r"(r[2]), "=r"(r[3]) : "r"(addr));
}
__device__ __forceinline__ void ldm_x4t(uint32_t* r, uint32_t addr){
  asm volatile("ldmatrix.sync.aligned.m8n8.x4.trans.shared.b16 {%0,%1,%2,%3}, [%4];"
    : "=r"(r[0]), "=r"(r[1]), "=r"(r[2]), "=r"(r[3]) : "r"(addr));
}
__device__ __forceinline__ void mma_f16(float* c, const uint32_t* a, uint32_t b0, uint32_t b1){
  asm volatile(
    "mma.sync.aligned.m16n8k16.row.col.f32.f16.f16.f32 "
    "{%0,%1,%2,%3}, {%4,%5,%6,%7}, {%8,%9}, {%0,%1,%2,%3};"
    : "+f"(c[0]), "+f"(c[1]), "+f"(c[2]), "+f"(c[3])
    : "r"(a[0]), "r"(a[1]), "r"(a[2]), "r"(a[3]), "r"(b0), "r"(b1));
}

// ---------------- 1) adjacency (fp32 + fp16) ----------------
__global__ void k_adj(const float* __restrict__ E){
  int i = blockIdx.x, j = threadIdx.x;
  __shared__ float Ei[16];
  __shared__ float red[512];
  if (j < 16) Ei[j] = E[i*16 + j];
  __syncthreads();
  float d = 0.f;
  #pragma unroll
  for (int c = 0; c < 16; c++) d = fmaf(Ei[c], E[j*16 + c], d);
  d = fmaxf(d, 0.f);
  red[j] = d; __syncthreads();
  for (int s = 256; s > 0; s >>= 1){ if (j < s) red[j] = fmaxf(red[j], red[j+s]); __syncthreads(); }
  float mx = red[0];
  __syncthreads();
  float e = __expf(d - mx);
  red[j] = e; __syncthreads();
  for (int s = 256; s > 0; s >>= 1){ if (j < s) red[j] += red[j+s]; __syncthreads(); }
  float a = e * (1.f / red[0]);
  g_Af32[i*512 + j] = a;
  g_Af[i*512 + j] = __float2half_rn(a);
}

// ---------------- 1b) M2 = 2*A@A -> fp16 ----------------
__global__ void k_a2(){
  int row0 = blockIdx.x * 128, col0 = blockIdx.y * 64;
  __shared__ float As[128][17];
  __shared__ __align__(16) float Bs[16][64];
  int tid = threadIdx.x;
  int tx = tid & 7, ty = tid >> 3;
  float acc[8][8];
  #pragma unroll
  for (int i=0;i<8;i++)
    #pragma unroll
    for (int j=0;j<8;j++) acc[i][j] = 0.f;
  for (int k0 = 0; k0 < 512; k0 += 16){
    #pragma unroll
    for (int i = 0; i < 4; i++){
      int idx = tid + i*128;
      int r = idx >> 2, kq = idx & 3;
      float4 a4 = *(const float4*)(g_Af32 + (size_t)(row0 + r)*512 + k0 + kq*4);
      As[r][kq*4+0]=a4.x; As[r][kq*4+1]=a4.y; As[r][kq*4+2]=a4.z; As[r][kq*4+3]=a4.w;
    }
    #pragma unroll
    for (int i = 0; i < 2; i++){
      int idx = tid + i*128;
      int r = idx >> 4, cq = idx & 15;
      float4 b4 = *(const float4*)(g_Af32 + (size_t)(k0 + r)*512 + col0 + cq*4);
      *(float4*)&Bs[r][cq*4] = b4;
    }
    __syncthreads();
    #pragma unroll
    for (int k = 0; k < 16; k++){
      float a[8], b[8];
      #pragma unroll
      for (int i=0;i<8;i++) a[i] = As[ty*8+i][k];
      float4 b0 = *(const float4*)&Bs[k][tx*8];
      float4 b1 = *(const float4*)&Bs[k][tx*8+4];
      b[0]=b0.x; b[1]=b0.y; b[2]=b0.z; b[3]=b0.w;
      b[4]=b1.x; b[5]=b1.y; b[6]=b1.z; b[7]=b1.w;
      #pragma unroll
      for (int i=0;i<8;i++)
        #pragma unroll
        for (int j=0;j<8;j++) acc[i][j] = fmaf(a[i], b[j], acc[i][j]);
    }
    __syncthreads();
  }
  #pragma unroll
  for (int i=0;i<8;i++){
    size_t r = row0 + ty*8 + i;
    #pragma unroll
    for (int j=0;j<8;j++)
      g_M2f[r*512 + col0 + tx*8 + j] = __float2half_rn(2.f * acc[i][j]);
  }
}

// ---------------- 2) fused prep + qkvu + attention -> de (fp32 + fp16) ----------------
constexpr int QA_OX  = 0;
constexpr int QA_OB  = 4352;
constexpr int QA_OQ  = 8704;
constexpr int QA_OPQ = 25344;
constexpr int QA_OPK = 26112;
constexpr int QA_OPV = 26176;
constexpr int QA_OES = 26240;
constexpr int QA_SMB = 27008 * 4;

__global__ void __launch_bounds__(256, 2) k_qa(
    const float* __restrict__ hn, const float* __restrict__ ne1, const float* __restrict__ ne2,
    const float* __restrict__ Wq, const float* __restrict__ bq,
    const float* __restrict__ Wk, const float* __restrict__ bk,
    const float* __restrict__ Wv, const float* __restrict__ bv,
    const float* __restrict__ taw, const float* __restrict__ tab){
  extern __shared__ float sm[];
  float* Xs = sm + QA_OX;
  float* Bs = sm + QA_OB;
  float* Q  = sm + QA_OQ;
  float* pq = sm + QA_OPQ;
  float* pk = sm + QA_OPK;
  float* pv = sm + QA_OPV;
  float* es = sm + QA_OES;
  int tid = threadIdx.x;
  int bn0 = blockIdx.x * 64;
  int b = bn0 >> 9;

  #pragma unroll
  for (int i = tid; i < 64*16; i += 256){
    int r = i >> 4, q = i & 15;
    float4 v = *(const float4*)(hn + (size_t)(bn0 + r)*64 + q*4);
    Xs[r*68 + q*4+0]=v.x; Xs[r*68 + q*4+1]=v.y; Xs[r*68 + q*4+2]=v.z; Xs[r*68 + q*4+3]=v.w;
  }
  const float* e1 = ne1 + (size_t)(b*12 + 11)*32;
  if (tid < 64){
    float a = bk[tid];
    #pragma unroll
    for (int d = 0; d < 32; d++) a = fmaf(e1[d], Wk[d*64 + tid], a);
    pk[tid] = a;
  } else if (tid < 128){
    int o = tid - 64;
    float a = bv[o];
    #pragma unroll
    for (int d = 0; d < 32; d++) a = fmaf(e1[d], Wv[d*64 + o], a);
    pv[o] = a;
  }
  for (int i = tid; i < 768; i += 256){
    int t = i >> 6, o = i & 63;
    const float* e2 = ne2 + (size_t)(b*12 + t)*32;
    float a = bq[o];
    #pragma unroll
    for (int d = 0; d < 32; d++) a = fmaf(e2[d], Wq[d*64 + o], a);
    pq[t*64 + o] = a;
  }
  __syncthreads();

  int ty = tid >> 4, tx = tid & 15;
  for (int mode = 0; mode < 4; mode++){
    const float* Wsrc = (mode==0) ? Wq + 2048 : (mode==1) ? Wk + 2048
                      : (mode==2) ? Wv + 2048 : taw;
    #pragma unroll
    for (int i = tid; i < 64*16; i += 256){
      int r = i >> 4, q = i & 15;
      float4 w4 = *(const float4*)(Wsrc + (size_t)r*64 + q*4);
      Bs[r*68 + q*4+0]=w4.x; Bs[r*68 + q*4+1]=w4.y; Bs[r*68 + q*4+2]=w4.z; Bs[r*68 + q*4+3]=w4.w;
    }
    __syncthreads();
    float acc[4][4];
    #pragma unroll
    for (int i=0;i<4;i++){ acc[i][0]=0.f; acc[i][1]=0.f; acc[i][2]=0.f; acc[i][3]=0.f; }
    #pragma unroll 16
    for (int k = 0; k < 64; k++){
      float a[4], bb[4];
      #pragma unroll
      for (int i=0;i<4;i++) a[i] = Xs[(ty*4+i)*68 + k];
      #pragma unroll
      for (int j=0;j<4;j++) bb[j] = Bs[k*68 + tx*4+j];
      #pragma unroll
      for (int i=0;i<4;i++)
        #pragma unroll
        for (int j=0;j<4;j++) acc[i][j] = fmaf(a[i], bb[j], acc[i][j]);
    }
    #pragma unroll
    for (int i=0;i<4;i++){
      int r = ty*4 + i;
      #pragma unroll
      for (int j=0;j<4;j++){
        int c = tx*4 + j;
        float v = acc[i][j];
        if (mode == 1)      v = fmaxf(v + pk[c], 0.f);
        else if (mode == 2) v = fmaxf(v + pv[c], 0.f);
        else if (mode == 3) v = v + tab[c];
        Q[r*260 + mode*64 + c] = v;
      }
    }
    __syncthreads();
  }
  for (int i = tid; i < 4096; i += 256) Bs[(i>>6)*68 + (i&63)] = taw[4096 + i];
  __syncthreads();

  int w = tid >> 5, lane = tid & 31;
  float* esw = es + w*96;
  int c0 = lane*2;
  for (int i = 0; i < 8; i++){
    int lr = w*8 + i;
    int n = (bn0 + lr) & 511;
    const float* q_ = Q + lr*260;
    float u0 = q_[192+c0], u1 = q_[193+c0];
    float vw0[8], vw1[8];
    #pragma unroll
    for (int d = 0; d < 8; d++){
      float a0 = 0.f, a1 = 0.f;
      #pragma unroll
      for (int cp = 0; cp < 8; cp++){
        float vv = q_[128 + d*8 + cp];
        float2 t2 = *(const float2*)&Bs[(d*8+cp)*68 + c0];
        a0 = fmaf(vv, t2.x, a0); a1 = fmaf(vv, t2.y, a1);
      }
      vw0[d] = a0; vw1[d] = a1;
    }
    for (int task = lane; task < 96; task += 32){
      int d = task / 12, t = task - d*12;
      const float* pqd = pq + t*64 + d*8;
      float e = 0.f;
      #pragma unroll
      for (int cp = 0; cp < 8; cp++){
        float qv = fmaxf(q_[d*8+cp] + pqd[cp], 0.f);
        e = fmaf(qv, q_[64 + d*8 + cp], e);
      }
      esw[d*12 + t] = e;
    }
    __syncwarp();
    if (lane < 8){
      float mx = -1e30f;
      #pragma unroll
      for (int t=0;t<12;t++) mx = fmaxf(mx, esw[lane*12 + t]);
      float ssum = 0.f;
      #pragma unroll
      for (int t=0;t<12;t++){ float ex = __expf(esw[lane*12+t]-mx); esw[lane*12+t]=ex; ssum+=ex; }
      float inv = 1.f/ssum;
      #pragma unroll
      for (int t=0;t<12;t++) esw[lane*12+t] *= inv;
    }
    __syncwarp();
    #pragma unroll
    for (int t = 0; t < 12; t++){
      float o0 = u0, o1 = u1;
      #pragma unroll
      for (int d = 0; d < 8; d++){
        float a = esw[d*12 + t];
        o0 = fmaf(a, vw0[d], o0); o1 = fmaf(a, vw1[d], o1);
      }
      size_t off = ((size_t)(b*12 + t)*512 + n)*64;
      *(float2*)(g_de + off + c0) = make_float2(o0, o1);
      __half2 hv; hv.x = __float2half_rn(o0); hv.y = __float2half_rn(o1);
      *(__half2*)(g_def + off + c0) = hv;
    }
    __syncwarp();
  }
}

// ---------------- 3) weight gen -> fp16 W (dead row-0 dropped) + fp32 biases ----------------
__global__ void k_wgen(const float* __restrict__ Am, const float* __restrict__ Bw,
                       const float* __restrict__ g, int Nc, int dst){
  int col0 = blockIdx.x * 64, row0 = blockIdx.y * 64;
  __shared__ float As[64][33];
  __shared__ float Bs[32][65];
  int tid = threadIdx.x;
  #pragma unroll
  for (int i = 0; i < 2; i++){
    int idx = tid + i*256;
    { int r = idx >> 3, kq = idx & 7;
      float4 a4 = *(const float4*)(Am + (size_t)(row0 + r)*32 + kq*4);
      As[r][kq*4+0]=a4.x; As[r][kq*4+1]=a4.y; As[r][kq*4+2]=a4.z; As[r][kq*4+3]=a4.w; }
    { int r = idx >> 4, cq = idx & 15;
      float4 b4 = *(const float4*)(Bw + (size_t)r*Nc + col0 + cq*4);
      Bs[r][cq*4+0]=b4.x; Bs[r][cq*4+1]=b4.y; Bs[r][cq*4+2]=b4.z; Bs[r][cq*4+3]=b4.w; }
  }
  __syncthreads();
  int ty = tid >> 4, tx = tid & 15;
  float acc[4][4];
  #pragma unroll
  for (int i=0;i<4;i++){ acc[i][0]=0.f; acc[i][1]=0.f; acc[i][2]=0.f; acc[i][3]=0.f; }
  #pragma unroll
  for (int k = 0; k < 32; k++){
    float a[4], b[4];
    #pragma unroll
    for (int i=0;i<4;i++) a[i] = As[ty*4+i][k];
    #pragma unroll
    for (int j=0;j<4;j++) b[j] = Bs[k][tx*4+j];
    #pragma unroll
    for (int i=0;i<4;i++)
      #pragma unroll
      for (int j=0;j<4;j++) acc[i][j] = fmaf(a[i], b[j], acc[i][j]);
  }
  int No = (dst==0) ? 128 : 64;
  int GNo = 65*No;
  #pragma unroll
  for (int i=0;i<4;i++){
    int r = row0 + ty*4 + i;
    #pragma unroll
    for (int j=0;j<4;j++){
      int c = col0 + tx*4 + j;
      float v = acc[i][j] + g[c];
      if (dst == 2)      g_b1[(size_t)r*128 + c] = v;
      else if (dst == 3) g_bu[(size_t)r*64 + c] = v;
      else {
        int seg = c / GNo, rem = c - seg*GNo;
        int ki = rem / No, o = rem - ki*No;
        if (ki >= 1){
          size_t off = (((size_t)r*3 + seg)*64 + (ki-1))*No + o;
          if (dst == 0) g_W1f[off] = __float2half_rn(v);
          else          g_Wuf[off] = __float2half_rn(v);
        }
      }
    }
  }
}

// ---------------- 4) single-output HMMA fp16 (split dual GEMM; grid z = which output) ----------------
// z=0: y1 = A@X ;  z=1: y2 = M2@X - X   (BK=32, 16 chunks, 3-stage, 3 CTAs/SM)
constexpr int STG_SZ = 14848;     // A: 128x80B = 10240 ; X: 32x144B = 4608
constexpr int OA = 0, OX = 10240;
constexpr int SMB = 3 * STG_SZ;   // 44544

__global__ void __launch_bounds__(256, 3) k_bmma2(int from_yz){
  extern __shared__ __align__(16) char dynsm[];
  uint32_t sb = s2u(dynsm);
  int mode = blockIdx.z;
  const __half* __restrict__ Asrc = mode ? g_M2f : g_Af;
  const __half* __restrict__ Xf = from_yz ? g_yzf : g_def;
  __half* __restrict__ Out = mode ? g_y2f : g_y1f;

  int bt = blockIdx.y, m0 = blockIdx.x * 128;
  int tid = threadIdx.x, wid = tid >> 5, lane = tid & 31;
  int warp_m = wid >> 1, warp_n = wid & 1;

  int arow = tid >> 2, aq = tid & 3;   // A: 128 rows x 4 x 16B (2 rows/thread)
  int xr = tid >> 3, xq = tid & 7;     // X: 32 rows x 8 x 16B (1/thread)

  auto load_chunk = [&](int c, int st){
    uint32_t base = sb + (uint32_t)st * STG_SZ;
    int k0 = c * 32;
    #pragma unroll
    for (int rr = 0; rr < 128; rr += 64){
      int row = arow + rr;
      size_t ga = (size_t)(m0 + row)*512 + k0 + aq*8;
      cp16(base + OA + (uint32_t)row*80 + aq*16, Asrc + ga);
    }
    size_t gx = ((size_t)bt*512 + k0 + xr)*64 + xq*8;
    cp16(base + OX + (uint32_t)xr*144 + xq*16, Xf + gx);
  };

  float acc[2][4][4];
  #pragma unroll
  for (int mi=0;mi<2;mi++)
    #pragma unroll
    for (int nn=0;nn<4;nn++)
      #pragma unroll
      for (int j=0;j<4;j++) acc[mi][nn][j] = 0.f;

  load_chunk(0, 0);
  asm volatile("cp.async.commit_group;" ::: "memory");
  load_chunk(1, 1);
  asm volatile("cp.async.commit_group;" ::: "memory");

  uint32_t lrow = lane & 15;
  uint32_t lk = (lane >> 4) << 4;

  for (int c = 0; c < 16; c++){
    if (c < 15) asm volatile("cp.async.wait_group 1;" ::: "memory");
    else        asm volatile("cp.async.wait_group 0;" ::: "memory");
    __syncthreads();

    int st = c % 3;
    uint32_t base = sb + (uint32_t)st * STG_SZ;
    #pragma unroll
    for (int kh = 0; kh < 2; kh++){
      uint32_t bf[2][4];
      uint32_t boff = (uint32_t)kh*2304 + lrow*144 + (uint32_t)warp_n*64 + lk;
      #pragma unroll
      for (int np = 0; np < 2; np++)
        ldm_x4t(bf[np], base + OX + boff + np*32);
      #pragma unroll
      for (int mi = 0; mi < 2; mi++){
        uint32_t fa[4];
        ldm_x4(fa, base + OA + (uint32_t)(warp_m*32 + mi*16 + lrow)*80 + kh*32 + lk);
        #pragma unroll
        for (int nn = 0; nn < 4; nn++){
          int np = nn >> 1, sub = (nn & 1) * 2;
          mma_f16(acc[mi][nn], fa, bf[np][sub], bf[np][sub+1]);
        }
      }
    }
    if (c + 2 < 16){
      load_chunk(c + 2, (c + 2) % 3);
      asm volatile("cp.async.commit_group;" ::: "memory");
    }
  }

  int rbase = m0 + warp_m*32 + (lane >> 2);
  int cbase = warp_n*32 + (lane & 3)*2;
  #pragma unroll
  for (int mi = 0; mi < 2; mi++){
    #pragma unroll
    for (int nn = 0; nn < 4; nn++){
      int col = cbase + nn*8;
      #pragma unroll
      for (int half = 0; half < 2; half++){
        int row = rbase + mi*16 + half*8;
        size_t off = ((size_t)bt*512 + row)*64 + col;
        float v0 = acc[mi][nn][half*2], v1 = acc[mi][nn][half*2+1];
        if (mode){
          __half2 x2 = *(const __half2*)(Xf + off);
          v0 -= __half2float(x2.x);
          v1 -= __half2float(x2.y);
        }
        __half2 hv; hv.x = __float2half_rn(v0); hv.y = __float2half_rn(v1);
        *(__half2*)(Out + off) = hv;
      }
    }
  }
}

// ---------------- 5) HMMA fp16 combine (3-stage 1-sync; WHICH=1 fuses final projection) ----------------
template<int WHICH>
__global__ void __launch_bounds__(256, 2) k_combT(const float* __restrict__ outw,
                                                  const float* __restrict__ outb,
                                                  float* __restrict__ out){
  constexpr int No = WHICH ? 64 : 128;
  const __half* __restrict__ Y0f = WHICH ? g_yzf : g_def;
  const __half* __restrict__ Wf  = WHICH ? g_Wuf : g_W1f;

  __shared__ __half sA[3][128*24];
  __shared__ __half sX[3][16*72];
  __shared__ float spart[128][2];

  int bt = blockIdx.z, n0 = blockIdx.y * 128, ct = blockIdx.x;
  int tid = threadIdx.x, wid = tid >> 5, lane = tid & 31;
  int warp_m = wid >> 1, warp_n = wid & 1;

  uint32_t uA[3] = { s2u(sA[0]), s2u(sA[1]), s2u(sA[2]) };
  uint32_t uX[3] = { s2u(sX[0]), s2u(sX[1]), s2u(sX[2]) };

  int arow = tid >> 1, aq = tid & 1;
  int xr = (tid & 127) >> 3, xq = tid & 7;
  bool xload = tid < 128;

  auto load_chunk = [&](int c, int st){
    int seg = c >> 2, kin0 = (c & 3) * 16;
    const __half* Yf = seg==0 ? Y0f : seg==1 ? g_y1f : g_y2f;
    size_t ga = ((size_t)bt*512 + n0 + arow)*64 + kin0 + aq*8;
    cp16(uA[st] + arow*48 + aq*16, Yf + ga);
    if (xload){
      size_t gw = (((size_t)bt*3 + seg)*64 + kin0 + xr)*No + ct*64 + xq*8;
      cp16(uX[st] + xr*144 + xq*16, Wf + gw);
    }
  };

  float acc[2][4][4];
  #pragma unroll
  for (int mi=0;mi<2;mi++)
    #pragma unroll
    for (int nn=0;nn<4;nn++)
      #pragma unroll
      for (int j=0;j<4;j++) acc[mi][nn][j] = 0.f;

  load_chunk(0, 0);
  asm volatile("cp.async.commit_group;" ::: "memory");
  load_chunk(1, 1);
  asm volatile("cp.async.commit_group;" ::: "memory");

  uint32_t lrow = lane & 15;
  uint32_t lk = (lane >> 4) << 4;

  for (int c = 0; c < 12; c++){
    if (c < 11) asm volatile("cp.async.wait_group 1;" ::: "memory");
    else        asm volatile("cp.async.wait_group 0;" ::: "memory");
    __syncthreads();

    int st = c % 3;
    uint32_t af[2][4], bf[2][4];
    #pragma unroll
    for (int mi = 0; mi < 2; mi++)
      ldm_x4(af[mi], uA[st] + (uint32_t)(warp_m*32 + mi*16 + lrow)*48 + lk);
    #pragma unroll
    for (int np = 0; np < 2; np++)
      ldm_x4t(bf[np], uX[st] + lrow*144 + (uint32_t)(warp_n*32 + np*16)*2 + lk);
    #pragma unroll
    for (int mi = 0; mi < 2; mi++){
      #pragma unroll
      for (int nn = 0; nn < 4; nn++){
        int np = nn >> 1, sub = (nn & 1) * 2;
        mma_f16(acc[mi][nn], af[mi], bf[np][sub], bf[np][sub+1]);
      }
    }
    if (c + 2 < 12){
      load_chunk(c + 2, (c + 2) % 3);
      asm volatile("cp.async.commit_group;" ::: "memory");
    }
  }

  int rbase = n0 + warp_m*32 + (lane >> 2);
  int cbase = warp_n*32 + (lane & 3)*2;
  int t = bt % 12;
  float part[2][2] = {{0.f,0.f},{0.f,0.f}};
  #pragma unroll
  for (int mi = 0; mi < 2; mi++){
    #pragma unroll
    for (int nn = 0; nn < 4; nn++){
      int col = cbase + nn*8;
      int gcol = ct*64 + col;
      #pragma unroll
      for (int half = 0; half < 2; half++){
        int row = rbase + mi*16 + half*8;
        size_t off = ((size_t)bt*512 + row)*64 + col;
        float v0 = acc[mi][nn][half*2], v1 = acc[mi][nn][half*2+1];
        if (WHICH == 0){
          v0 += g_b1[(size_t)bt*128 + gcol];
          v1 += g_b1[(size_t)bt*128 + gcol + 1];
          v0 = 1.f/(1.f + __expf(-v0));
          v1 = 1.f/(1.f + __expf(-v1));
          if (ct == 0){
            float2 de = *(const float2*)(g_de + off);
            float z0 = v0 * de.x, z1 = v1 * de.y;
            __half2 hv; hv.x = __float2half_rn(z0); hv.y = __float2half_rn(z1);
            *(__half2*)(g_yzf + off) = hv;
          } else {
            *(float2*)(g_rg + off) = make_float2(v0, v1);
          }
        } else {
          float h0 = tanhf(v0 + g_bu[(size_t)bt*64 + gcol]);
          float h1 = tanhf(v1 + g_bu[(size_t)bt*64 + gcol + 1]);
          float2 rg2 = *(const float2*)(g_rg + off);
          float2 de2 = *(const float2*)(g_de + off);
          float st0 = fmaf(rg2.x, de2.x - h0, h0);
          float st1 = fmaf(rg2.y, de2.y - h1, h1);
          part[mi][half] += st0 * outw[t*64 + gcol] + st1 * outw[t*64 + gcol + 1];
        }
      }
    }
  }
  if (WHICH == 1){
    #pragma unroll
    for (int mi = 0; mi < 2; mi++)
      #pragma unroll
      for (int half = 0; half < 2; half++){
        float p = part[mi][half];
        p += __shfl_xor_sync(0xffffffffu, p, 1);
        p += __shfl_xor_sync(0xffffffffu, p, 2);
        if ((lane & 3) == 0){
          int rl = warp_m*32 + mi*16 + half*8 + (lane >> 2);
          spart[rl][warp_n] = p;
        }
      }
    __syncthreads();
    if (tid < 128)
      out[(size_t)bt*512 + n0 + tid] = spart[tid][0] + spart[tid][1] + outb[t];
  }
}

// ---------------- launch ----------------
extern "C" void kernel_launch(void* const* d_in, const int* in_sizes, int n_in,
                              void* d_out, int out_size){
  (void)in_sizes; (void)n_in; (void)out_size;
  const float* hn  = (const float*)d_in[2];
  const float* ne1 = (const float*)d_in[3];
  const float* ne2 = (const float*)d_in[4];
  const float* E   = (const float*)d_in[5];
  const float* Wq  = (const float*)d_in[6];
  const float* bq  = (const float*)d_in[7];
  const float* Wk  = (const float*)d_in[8];
  const float* bk  = (const float*)d_in[9];
  const float* Wv  = (const float*)d_in[10];
  const float* bv  = (const float*)d_in[11];
  const float* taw = (const float*)d_in[12];
  const float* tab = (const float*)d_in[13];
  const float* gwp = (const float*)d_in[14];
  const float* gw  = (const float*)d_in[15];
  const float* gbp = (const float*)d_in[16];
  const float* gb  = (const float*)d_in[17];
  const float* uwp = (const float*)d_in[18];
  const float* uw  = (const float*)d_in[19];
  const float* ubp = (const float*)d_in[20];
  const float* ub  = (const float*)d_in[21];
  const float* outw= (const float*)d_in[22];
  const float* outb= (const float*)d_in[23];
  float* out = (float*)d_out;

  cudaFuncSetAttribute(k_qa, cudaFuncAttributeMaxDynamicSharedMemorySize, QA_SMB);
  cudaFuncSetAttribute(k_bmma2, cudaFuncAttributeMaxDynamicSharedMemorySize, SMB);

  k_adj<<<512, 512>>>(E);
  k_a2<<<dim3(4, 8), 128>>>();
  k_qa<<<512, 256, QA_SMB>>>(hn, ne1, ne2, Wq, bq, Wk, bk, Wv, bv, taw, tab);
  k_bmma2<<<dim3(4, 768, 2), 256, SMB>>>(0);     // (profiled slot) y1 & y2 from de
  k_wgen<<<dim3(390, 12), 256>>>(ne2, gwp, gw, 24960, 0);
  k_wgen<<<dim3(195, 12), 256>>>(ne2, uwp, uw, 12480, 1);
  k_wgen<<<dim3(2, 12), 256>>>(ne2, gbp, gb, 128, 2);
  k_wgen<<<dim3(1, 12), 256>>>(ne2, ubp, ub, 64, 3);
  k_combT<0><<<dim3(2, 4, 768), 256>>>(nullptr, nullptr, nullptr);   // yzf / rg
  k_bmma2<<<dim3(4, 768, 2), 256, SMB>>>(1);     // y1 & y2 from yz
  k_combT<1><<<dim3(1, 4, 768), 256>>>(outw, outb, out);             // hc + final proj
}

// round 16
// speedup vs baseline: 2.2553x; 1.0898x over previous
#include <cuda_runtime.h>
#include <cuda_fp16.h>
#include <math.h>
#include <stdint.h>

// B=64, T=12, N=512, H=64, TD=32, ED=16, CHEB_K=3, D_HEADS=8, M=768
constexpr size_t NF = (size_t)768*512*64;

// ---------------- device scratch ----------------
__device__ float g_Af32[512*512];
__device__ __half g_Af[512*512], g_M2f[512*512];
__device__ float g_de[NF], g_rg[NF];
__device__ __half g_def[NF], g_y1f[NF], g_y2f[NF], g_yzf[NF];
__device__ __half g_W1f[(size_t)768*3*64*128];
__device__ __half g_Wuf[(size_t)768*3*64*64];
__device__ float g_b1[768*128], g_bu[768*64];

// ---------------- ptx helpers (sm_80+ baseline only) ----------------
__device__ __forceinline__ uint32_t s2u(const void* p){
  uint32_t a;
  asm("{ .reg .u64 t; cvta.to.shared.u64 t, %1; cvt.u32.u64 %0, t; }" : "=r"(a) : "l"(p));
  return a;
}
__device__ __forceinline__ void cp16(uint32_t dst, const void* src){
  asm volatile("cp.async.cg.shared.global [%0], [%1], 16;" :: "r"(dst), "l"(src) : "memory");
}
__device__ __forceinline__ void ldm_x4(uint32_t* r, uint32_t addr){
  asm volatile("ldmatrix.sync.aligned.m8n8.x4.shared.b16 {%0,%1,%2,%3}, [%4];"
    : "=r"(r[0]), "=r"(r[1]), "=r"(r[2]), "=r"(r[3]) : "r"(addr));
}
__device__ __forceinline__ void ldm_x4t(uint32_t* r, uint32_t addr){
  asm volatile("ldmatrix.sync.aligned.m8n8.x4.trans.shared.b16 {%0,%1,%2,%3}, [%4];"
    : "=r"(r[0]), "=r"(r[1]), "=r"(r[2]), "=r"(r[3]) : "r"(addr));
}
__device__ __forceinline__ void mma_f16(float* c, const uint32_t* a, uint32_t b0, uint32_t b1){
  asm volatile(
    "mma.sync.aligned.m16n8k16.row.col.f32.f16.f16.f32 "
    "{%0,%1,%2,%3}, {%4,%5,%6,%7}, {%8,%9}, {%0,%1,%2,%3};"
    : "+f"(c[0]), "+f"(c[1]), "+f"(c[2]), "+f"(c[3])
    : "r"(a[0]), "r"(a[1]), "r"(a[2]), "r"(a[3]), "r"(b0), "r"(b1));
}

// ---------------- 1) adjacency (fp32 + fp16) ----------------
__global__ void k_adj(const float* __restrict__ E){
  int i = blockIdx.x, j = threadIdx.x;
  __shared__ float Ei[16];
  __shared__ float red[512];
  if (j < 16) Ei[j] = E[i*16 + j];
  __syncthreads();
  float d = 0.f;
  #pragma unroll
  for (int c = 0; c < 16; c++) d = fmaf(Ei[c], E[j*16 + c], d);
  d = fmaxf(d, 0.f);
  red[j] = d; __syncthreads();
  for (int s = 256; s > 0; s >>= 1){ if (j < s) red[j] = fmaxf(red[j], red[j+s]); __syncthreads(); }
  float mx = red[0];
  __syncthreads();
  float e = __expf(d - mx);
  red[j] = e; __syncthreads();
  for (int s = 256; s > 0; s >>= 1){ if (j < s) red[j] += red[j+s]; __syncthreads(); }
  float a = e * (1.f / red[0]);
  g_Af32[i*512 + j] = a;
  g_Af[i*512 + j] = __float2half_rn(a);
}

// ---------------- 1b) M2 = 2*A@A -> fp16 ----------------
__global__ void k_a2(){
  int row0 = blockIdx.x * 128, col0 = blockIdx.y * 64;
  __shared__ float As[128][17];
  __shared__ __align__(16) float Bs[16][64];
  int tid = threadIdx.x;
  int tx = tid & 7, ty = tid >> 3;
  float acc[8][8];
  #pragma unroll
  for (int i=0;i<8;i++)
    #pragma unroll
    for (int j=0;j<8;j++) acc[i][j] = 0.f;
  for (int k0 = 0; k0 < 512; k0 += 16){
    #pragma unroll
    for (int i = 0; i < 4; i++){
      int idx = tid + i*128;
      int r = idx >> 2, kq = idx & 3;
      float4 a4 = *(const float4*)(g_Af32 + (size_t)(row0 + r)*512 + k0 + kq*4);
      As[r][kq*4+0]=a4.x; As[r][kq*4+1]=a4.y; As[r][kq*4+2]=a4.z; As[r][kq*4+3]=a4.w;
    }
    #pragma unroll
    for (int i = 0; i < 2; i++){
      int idx = tid + i*128;
      int r = idx >> 4, cq = idx & 15;
      float4 b4 = *(const float4*)(g_Af32 + (size_t)(k0 + r)*512 + col0 + cq*4);
      *(float4*)&Bs[r][cq*4] = b4;
    }
    __syncthreads();
    #pragma unroll
    for (int k = 0; k < 16; k++){
      float a[8], b[8];
      #pragma unroll
      for (int i=0;i<8;i++) a[i] = As[ty*8+i][k];
      float4 b0 = *(const float4*)&Bs[k][tx*8];
      float4 b1 = *(const float4*)&Bs[k][tx*8+4];
      b[0]=b0.x; b[1]=b0.y; b[2]=b0.z; b[3]=b0.w;
      b[4]=b1.x; b[5]=b1.y; b[6]=b1.z; b[7]=b1.w;
      #pragma unroll
      for (int i=0;i<8;i++)
        #pragma unroll
        for (int j=0;j<8;j++) acc[i][j] = fmaf(a[i], b[j], acc[i][j]);
    }
    __syncthreads();
  }
  #pragma unroll
  for (int i=0;i<8;i++){
    size_t r = row0 + ty*8 + i;
    #pragma unroll
    for (int j=0;j<8;j++)
      g_M2f[r*512 + col0 + tx*8 + j] = __float2half_rn(2.f * acc[i][j]);
  }
}

// ---------------- 2) fused prep + qkvu + attention -> de (fp32 + fp16) ----------------
constexpr int QA_OX  = 0;
constexpr int QA_OB  = 4352;
constexpr int QA_OQ  = 8704;
constexpr int QA_OPQ = 25344;
constexpr int QA_OPK = 26112;
constexpr int QA_OPV = 26176;
constexpr int QA_OES = 26240;
constexpr int QA_SMB = 27008 * 4;

__global__ void __launch_bounds__(256, 2) k_qa(
    const float* __restrict__ hn, const float* __restrict__ ne1, const float* __restrict__ ne2,
    const float* __restrict__ Wq, const float* __restrict__ bq,
    const float* __restrict__ Wk, const float* __restrict__ bk,
    const float* __restrict__ Wv, const float* __restrict__ bv,
    const float* __restrict__ taw, const float* __restrict__ tab){
  extern __shared__ float sm[];
  float* Xs = sm + QA_OX;
  float* Bs = sm + QA_OB;
  float* Q  = sm + QA_OQ;
  float* pq = sm + QA_OPQ;
  float* pk = sm + QA_OPK;
  float* pv = sm + QA_OPV;
  float* es = sm + QA_OES;
  int tid = threadIdx.x;
  int bn0 = blockIdx.x * 64;
  int b = bn0 >> 9;

  #pragma unroll
  for (int i = tid; i < 64*16; i += 256){
    int r = i >> 4, q = i & 15;
    float4 v = *(const float4*)(hn + (size_t)(bn0 + r)*64 + q*4);
    Xs[r*68 + q*4+0]=v.x; Xs[r*68 + q*4+1]=v.y; Xs[r*68 + q*4+2]=v.z; Xs[r*68 + q*4+3]=v.w;
  }
  const float* e1 = ne1 + (size_t)(b*12 + 11)*32;
  if (tid < 64){
    float a = bk[tid];
    #pragma unroll
    for (int d = 0; d < 32; d++) a = fmaf(e1[d], Wk[d*64 + tid], a);
    pk[tid] = a;
  } else if (tid < 128){
    int o = tid - 64;
    float a = bv[o];
    #pragma unroll
    for (int d = 0; d < 32; d++) a = fmaf(e1[d], Wv[d*64 + o], a);
    pv[o] = a;
  }
  for (int i = tid; i < 768; i += 256){
    int t = i >> 6, o = i & 63;
    const float* e2 = ne2 + (size_t)(b*12 + t)*32;
    float a = bq[o];
    #pragma unroll
    for (int d = 0; d < 32; d++) a = fmaf(e2[d], Wq[d*64 + o], a);
    pq[t*64 + o] = a;
  }
  __syncthreads();

  int ty = tid >> 4, tx = tid & 15;
  for (int mode = 0; mode < 4; mode++){
    const float* Wsrc = (mode==0) ? Wq + 2048 : (mode==1) ? Wk + 2048
                      : (mode==2) ? Wv + 2048 : taw;
    #pragma unroll
    for (int i = tid; i < 64*16; i += 256){
      int r = i >> 4, q = i & 15;
      float4 w4 = *(const float4*)(Wsrc + (size_t)r*64 + q*4);
      Bs[r*68 + q*4+0]=w4.x; Bs[r*68 + q*4+1]=w4.y; Bs[r*68 + q*4+2]=w4.z; Bs[r*68 + q*4+3]=w4.w;
    }
    __syncthreads();
    float acc[4][4];
    #pragma unroll
    for (int i=0;i<4;i++){ acc[i][0]=0.f; acc[i][1]=0.f; acc[i][2]=0.f; acc[i][3]=0.f; }
    #pragma unroll 16
    for (int k = 0; k < 64; k++){
      float a[4], bb[4];
      #pragma unroll
      for (int i=0;i<4;i++) a[i] = Xs[(ty*4+i)*68 + k];
      #pragma unroll
      for (int j=0;j<4;j++) bb[j] = Bs[k*68 + tx*4+j];
      #pragma unroll
      for (int i=0;i<4;i++)
        #pragma unroll
        for (int j=0;j<4;j++) acc[i][j] = fmaf(a[i], bb[j], acc[i][j]);
    }
    #pragma unroll
    for (int i=0;i<4;i++){
      int r = ty*4 + i;
      #pragma unroll
      for (int j=0;j<4;j++){
        int c = tx*4 + j;
        float v = acc[i][j];
        if (mode == 1)      v = fmaxf(v + pk[c], 0.f);
        else if (mode == 2) v = fmaxf(v + pv[c], 0.f);
        else if (mode == 3) v = v + tab[c];
        Q[r*260 + mode*64 + c] = v;
      }
    }
    __syncthreads();
  }
  for (int i = tid; i < 4096; i += 256) Bs[(i>>6)*68 + (i&63)] = taw[4096 + i];
  __syncthreads();

  int w = tid >> 5, lane = tid & 31;
  float* esw = es + w*96;
  int c0 = lane*2;
  for (int i = 0; i < 8; i++){
    int lr = w*8 + i;
    int n = (bn0 + lr) & 511;
    const float* q_ = Q + lr*260;
    float u0 = q_[192+c0], u1 = q_[193+c0];
    float vw0[8], vw1[8];
    #pragma unroll
    for (int d = 0; d < 8; d++){
      float a0 = 0.f, a1 = 0.f;
      #pragma unroll
      for (int cp = 0; cp < 8; cp++){
        float vv = q_[128 + d*8 + cp];
        float2 t2 = *(const float2*)&Bs[(d*8+cp)*68 + c0];
        a0 = fmaf(vv, t2.x, a0); a1 = fmaf(vv, t2.y, a1);
      }
      vw0[d] = a0; vw1[d] = a1;
    }
    for (int task = lane; task < 96; task += 32){
      int d = task / 12, t = task - d*12;
      const float* pqd = pq + t*64 + d*8;
      float e = 0.f;
      #pragma unroll
      for (int cp = 0; cp < 8; cp++){
        float qv = fmaxf(q_[d*8+cp] + pqd[cp], 0.f);
        e = fmaf(qv, q_[64 + d*8 + cp], e);
      }
      esw[d*12 + t] = e;
    }
    __syncwarp();
    if (lane < 8){
      float mx = -1e30f;
      #pragma unroll
      for (int t=0;t<12;t++) mx = fmaxf(mx, esw[lane*12 + t]);
      float ssum = 0.f;
      #pragma unroll
      for (int t=0;t<12;t++){ float ex = __expf(esw[lane*12+t]-mx); esw[lane*12+t]=ex; ssum+=ex; }
      float inv = 1.f/ssum;
      #pragma unroll
      for (int t=0;t<12;t++) esw[lane*12+t] *= inv;
    }
    __syncwarp();
    #pragma unroll
    for (int t = 0; t < 12; t++){
      float o0 = u0, o1 = u1;
      #pragma unroll
      for (int d = 0; d < 8; d++){
        float a = esw[d*12 + t];
        o0 = fmaf(a, vw0[d], o0); o1 = fmaf(a, vw1[d], o1);
      }
      size_t off = ((size_t)(b*12 + t)*512 + n)*64;
      *(float2*)(g_de + off + c0) = make_float2(o0, o1);
      __half2 hv; hv.x = __float2half_rn(o0); hv.y = __float2half_rn(o1);
      *(__half2*)(g_def + off + c0) = hv;
    }
    __syncwarp();
  }
}

// ---------------- 3) weight gen -> fp16 W (dead row-0 dropped) + fp32 biases ----------------
__global__ void k_wgen(const float* __restrict__ Am, const float* __restrict__ Bw,
                       const float* __restrict__ g, int Nc, int dst){
  int col0 = blockIdx.x * 64, row0 = blockIdx.y * 64;
  __shared__ float As[64][33];
  __shared__ float Bs[32][65];
  int tid = threadIdx.x;
  #pragma unroll
  for (int i = 0; i < 2; i++){
    int idx = tid + i*256;
    { int r = idx >> 3, kq = idx & 7;
      float4 a4 = *(const float4*)(Am + (size_t)(row0 + r)*32 + kq*4);
      As[r][kq*4+0]=a4.x; As[r][kq*4+1]=a4.y; As[r][kq*4+2]=a4.z; As[r][kq*4+3]=a4.w; }
    { int r = idx >> 4, cq = idx & 15;
      float4 b4 = *(const float4*)(Bw + (size_t)r*Nc + col0 + cq*4);
      Bs[r][cq*4+0]=b4.x; Bs[r][cq*4+1]=b4.y; Bs[r][cq*4+2]=b4.z; Bs[r][cq*4+3]=b4.w; }
  }
  __syncthreads();
  int ty = tid >> 4, tx = tid & 15;
  float acc[4][4];
  #pragma unroll
  for (int i=0;i<4;i++){ acc[i][0]=0.f; acc[i][1]=0.f; acc[i][2]=0.f; acc[i][3]=0.f; }
  #pragma unroll
  for (int k = 0; k < 32; k++){
    float a[4], b[4];
    #pragma unroll
    for (int i=0;i<4;i++) a[i] = As[ty*4+i][k];
    #pragma unroll
    for (int j=0;j<4;j++) b[j] = Bs[k][tx*4+j];
    #pragma unroll
    for (int i=0;i<4;i++)
      #pragma unroll
      for (int j=0;j<4;j++) acc[i][j] = fmaf(a[i], b[j], acc[i][j]);
  }
  int No = (dst==0) ? 128 : 64;
  int GNo = 65*No;
  #pragma unroll
  for (int i=0;i<4;i++){
    int r = row0 + ty*4 + i;
    #pragma unroll
    for (int j=0;j<4;j++){
      int c = col0 + tx*4 + j;
      float v = acc[i][j] + g[c];
      if (dst == 2)      g_b1[(size_t)r*128 + c] = v;
      else if (dst == 3) g_bu[(size_t)r*64 + c] = v;
      else {
        int seg = c / GNo, rem = c - seg*GNo;
        int ki = rem / No, o = rem - ki*No;
        if (ki >= 1){
          size_t off = (((size_t)r*3 + seg)*64 + (ki-1))*No + o;
          if (dst == 0) g_W1f[off] = __float2half_rn(v);
          else          g_Wuf[off] = __float2half_rn(v);
        }
      }
    }
  }
}

// ---------------- 4) HMMA fp16, 2 batches per CTA (tile 128x128), z = output kind ----------------
// z=0: y1 = A@X(bt0),A@X(bt0+1) ; z=1: y2 = M2@X - X  (BK=32, 16 chunks, 3-stage)
constexpr int STG_SZ = 19456;     // A: 128x80B = 10240 ; X: 2 x 32x144B = 9216
constexpr int OA = 0, OX = 10240;
constexpr int SMB = 3 * STG_SZ;   // 58368

__global__ void __launch_bounds__(256, 2) k_bmma2(int from_yz){
  extern __shared__ __align__(16) char dynsm[];
  uint32_t sb = s2u(dynsm);
  int mode = blockIdx.z;
  const __half* __restrict__ Asrc = mode ? g_M2f : g_Af;
  const __half* __restrict__ Xf = from_yz ? g_yzf : g_def;
  __half* __restrict__ Out = mode ? g_y2f : g_y1f;

  int bt0 = blockIdx.y * 2, m0 = blockIdx.x * 128;
  int tid = threadIdx.x, wid = tid >> 5, lane = tid & 31;
  int warp_m = wid >> 1, warp_n = wid & 1;     // warp_n = batch within pair

  int arow = tid >> 2, aq = tid & 3;   // A: 128 rows x 4 x 16B (2 rows/thread)
  int xr = tid >> 3, xq = tid & 7;     // X: 32 rows x 8 x 16B per batch

  auto load_chunk = [&](int c, int st){
    uint32_t base = sb + (uint32_t)st * STG_SZ;
    int k0 = c * 32;
    #pragma unroll
    for (int rr = 0; rr < 128; rr += 64){
      int row = arow + rr;
      size_t ga = (size_t)(m0 + row)*512 + k0 + aq*8;
      cp16(base + OA + (uint32_t)row*80 + aq*16, Asrc + ga);
    }
    #pragma unroll
    for (int bb = 0; bb < 2; bb++){
      size_t gx = ((size_t)(bt0 + bb)*512 + k0 + xr)*64 + xq*8;
      cp16(base + OX + (uint32_t)bb*4608 + (uint32_t)xr*144 + xq*16, Xf + gx);
    }
  };

  float acc[2][8][4];
  #pragma unroll
  for (int mi=0;mi<2;mi++)
    #pragma unroll
    for (int nn=0;nn<8;nn++)
      #pragma unroll
      for (int j=0;j<4;j++) acc[mi][nn][j] = 0.f;

  load_chunk(0, 0);
  asm volatile("cp.async.commit_group;" ::: "memory");
  load_chunk(1, 1);
  asm volatile("cp.async.commit_group;" ::: "memory");

  uint32_t lrow = lane & 15;
  uint32_t lk = (lane >> 4) << 4;

  for (int c = 0; c < 16; c++){
    if (c < 15) asm volatile("cp.async.wait_group 1;" ::: "memory");
    else        asm volatile("cp.async.wait_group 0;" ::: "memory");
    __syncthreads();

    int st = c % 3;
    uint32_t base = sb + (uint32_t)st * STG_SZ;
    #pragma unroll
    for (int kh = 0; kh < 2; kh++){
      uint32_t bf[4][4];
      uint32_t xb = base + OX + (uint32_t)warp_n*4608 + (uint32_t)kh*2304 + lrow*144 + lk;
      #pragma unroll
      for (int np = 0; np < 4; np++)
        ldm_x4t(bf[np], xb + np*32);
      #pragma unroll
      for (int mi = 0; mi < 2; mi++){
        uint32_t fa[4];
        ldm_x4(fa, base + OA + (uint32_t)(warp_m*32 + mi*16 + lrow)*80 + kh*32 + lk);
        #pragma unroll
        for (int nn = 0; nn < 8; nn++){
          int np = nn >> 1, sub = (nn & 1) * 2;
          mma_f16(acc[mi][nn], fa, bf[np][sub], bf[np][sub+1]);
        }
      }
    }
    if (c + 2 < 16){
      load_chunk(c + 2, (c + 2) % 3);
      asm volatile("cp.async.commit_group;" ::: "memory");
    }
  }

  int bt = bt0 + warp_n;
  int rbase = m0 + warp_m*32 + (lane >> 2);
  int cbase = (lane & 3)*2;
  #pragma unroll
  for (int mi = 0; mi < 2; mi++){
    #pragma unroll
    for (int nn = 0; nn < 8; nn++){
      int col = cbase + nn*8;
      #pragma unroll
      for (int half = 0; half < 2; half++){
        int row = rbase + mi*16 + half*8;
        size_t off = ((size_t)bt*512 + row)*64 + col;
        float v0 = acc[mi][nn][half*2], v1 = acc[mi][nn][half*2+1];
        if (mode){
          __half2 x2 = *(const __half2*)(Xf + off);
          v0 -= __half2float(x2.x);
          v1 -= __half2float(x2.y);
        }
        __half2 hv; hv.x = __float2half_rn(v0); hv.y = __float2half_rn(v1);
        *(__half2*)(Out + off) = hv;
      }
    }
  }
}

// ---------------- 5) HMMA fp16 combine (3-stage 1-sync; WHICH=1 fuses final projection) ----------------
template<int WHICH>
__global__ void __launch_bounds__(256, 2) k_combT(const float* __restrict__ outw,
                                                  const float* __restrict__ outb,
                                                  float* __restrict__ out){
  constexpr int No = WHICH ? 64 : 128;
  const __half* __restrict__ Y0f = WHICH ? g_yzf : g_def;
  const __half* __restrict__ Wf  = WHICH ? g_Wuf : g_W1f;

  __shared__ __half sA[3][128*24];
  __shared__ __half sX[3][16*72];
  __shared__ float spart[128][2];

  int bt = blockIdx.z, n0 = blockIdx.y * 128, ct = blockIdx.x;
  int tid = threadIdx.x, wid = tid >> 5, lane = tid & 31;
  int warp_m = wid >> 1, warp_n = wid & 1;

  uint32_t uA[3] = { s2u(sA[0]), s2u(sA[1]), s2u(sA[2]) };
  uint32_t uX[3] = { s2u(sX[0]), s2u(sX[1]), s2u(sX[2]) };

  int arow = tid >> 1, aq = tid & 1;
  int xr = (tid & 127) >> 3, xq = tid & 7;
  bool xload = tid < 128;

  auto load_chunk = [&](int c, int st){
    int seg = c >> 2, kin0 = (c & 3) * 16;
    const __half* Yf = seg==0 ? Y0f : seg==1 ? g_y1f : g_y2f;
    size_t ga = ((size_t)bt*512 + n0 + arow)*64 + kin0 + aq*8;
    cp16(uA[st] + arow*48 + aq*16, Yf + ga);
    if (xload){
      size_t gw = (((size_t)bt*3 + seg)*64 + kin0 + xr)*No + ct*64 + xq*8;
      cp16(uX[st] + xr*144 + xq*16, Wf + gw);
    }
  };

  float acc[2][4][4];
  #pragma unroll
  for (int mi=0;mi<2;mi++)
    #pragma unroll
    for (int nn=0;nn<4;nn++)
      #pragma unroll
      for (int j=0;j<4;j++) acc[mi][nn][j] = 0.f;

  load_chunk(0, 0);
  asm volatile("cp.async.commit_group;" ::: "memory");
  load_chunk(1, 1);
  asm volatile("cp.async.commit_group;" ::: "memory");

  uint32_t lrow = lane & 15;
  uint32_t lk = (lane >> 4) << 4;

  for (int c = 0; c < 12; c++){
    if (c < 11) asm volatile("cp.async.wait_group 1;" ::: "memory");
    else        asm volatile("cp.async.wait_group 0;" ::: "memory");
    __syncthreads();

    int st = c % 3;
    uint32_t af[2][4], bf[2][4];
    #pragma unroll
    for (int mi = 0; mi < 2; mi++)
      ldm_x4(af[mi], uA[st] + (uint32_t)(warp_m*32 + mi*16 + lrow)*48 + lk);
    #pragma unroll
    for (int np = 0; np < 2; np++)
      ldm_x4t(bf[np], uX[st] + lrow*144 + (uint32_t)(warp_n*32 + np*16)*2 + lk);
    #pragma unroll
    for (int mi = 0; mi < 2; mi++){
      #pragma unroll
      for (int nn = 0; nn < 4; nn++){
        int np = nn >> 1, sub = (nn & 1) * 2;
        mma_f16(acc[mi][nn], af[mi], bf[np][sub], bf[np][sub+1]);
      }
    }
    if (c + 2 < 12){
      load_chunk(c + 2, (c + 2) % 3);
      asm volatile("cp.async.commit_group;" ::: "memory");
    }
  }

  int rbase = n0 + warp_m*32 + (lane >> 2);
  int cbase = warp_n*32 + (lane & 3)*2;
  int t = bt % 12;
  float part[2][2] = {{0.f,0.f},{0.f,0.f}};
  #pragma unroll
  for (int mi = 0; mi < 2; mi++){
    #pragma unroll
    for (int nn = 0; nn < 4; nn++){
      int col = cbase + nn*8;
      int gcol = ct*64 + col;
      #pragma unroll
      for (int half = 0; half < 2; half++){
        int row = rbase + mi*16 + half*8;
        size_t off = ((size_t)bt*512 + row)*64 + col;
        float v0 = acc[mi][nn][half*2], v1 = acc[mi][nn][half*2+1];
        if (WHICH == 0){
          v0 += g_b1[(size_t)bt*128 + gcol];
          v1 += g_b1[(size_t)bt*128 + gcol + 1];
          v0 = 1.f/(1.f + __expf(-v0));
          v1 = 1.f/(1.f + __expf(-v1));
          if (ct == 0){
            float2 de = *(const float2*)(g_de + off);
            float z0 = v0 * de.x, z1 = v1 * de.y;
            __half2 hv; hv.x = __float2half_rn(z0); hv.y = __float2half_rn(z1);
            *(__half2*)(g_yzf + off) = hv;
          } else {
            *(float2*)(g_rg + off) = make_float2(v0, v1);
          }
        } else {
          float h0 = tanhf(v0 + g_bu[(size_t)bt*64 + gcol]);
          float h1 = tanhf(v1 + g_bu[(size_t)bt*64 + gcol + 1]);
          float2 rg2 = *(const float2*)(g_rg + off);
          float2 de2 = *(const float2*)(g_de + off);
          float st0 = fmaf(rg2.x, de2.x - h0, h0);
          float st1 = fmaf(rg2.y, de2.y - h1, h1);
          part[mi][half] += st0 * outw[t*64 + gcol] + st1 * outw[t*64 + gcol + 1];
        }
      }
    }
  }
  if (WHICH == 1){
    #pragma unroll
    for (int mi = 0; mi < 2; mi++)
      #pragma unroll
      for (int half = 0; half < 2; half++){
        float p = part[mi][half];
        p += __shfl_xor_sync(0xffffffffu, p, 1);
        p += __shfl_xor_sync(0xffffffffu, p, 2);
        if ((lane & 3) == 0){
          int rl = warp_m*32 + mi*16 + half*8 + (lane >> 2);
          spart[rl][warp_n] = p;
        }
      }
    __syncthreads();
    if (tid < 128)
      out[(size_t)bt*512 + n0 + tid] = spart[tid][0] + spart[tid][1] + outb[t];
  }
}

// ---------------- launch ----------------
extern "C" void kernel_launch(void* const* d_in, const int* in_sizes, int n_in,
                              void* d_out, int out_size){
  (void)in_sizes; (void)n_in; (void)out_size;
  const float* hn  = (const float*)d_in[2];
  const float* ne1 = (const float*)d_in[3];
  const float* ne2 = (const float*)d_in[4];
  const float* E   = (const float*)d_in[5];
  const float* Wq  = (const float*)d_in[6];
  const float* bq  = (const float*)d_in[7];
  const float* Wk  = (const float*)d_in[8];
  const float* bk  = (const float*)d_in[9];
  const float* Wv  = (const float*)d_in[10];
  const float* bv  = (const float*)d_in[11];
  const float* taw = (const float*)d_in[12];
  const float* tab = (const float*)d_in[13];
  const float* gwp = (const float*)d_in[14];
  const float* gw  = (const float*)d_in[15];
  const float* gbp = (const float*)d_in[16];
  const float* gb  = (const float*)d_in[17];
  const float* uwp = (const float*)d_in[18];
  const float* uw  = (const float*)d_in[19];
  const float* ubp = (const float*)d_in[20];
  const float* ub  = (const float*)d_in[21];
  const float* outw= (const float*)d_in[22];
  const float* outb= (const float*)d_in[23];
  float* out = (float*)d_out;

  cudaFuncSetAttribute(k_qa, cudaFuncAttributeMaxDynamicSharedMemorySize, QA_SMB);
  cudaFuncSetAttribute(k_bmma2, cudaFuncAttributeMaxDynamicSharedMemorySize, SMB);

  k_adj<<<512, 512>>>(E);
  k_a2<<<dim3(4, 8), 128>>>();
  k_qa<<<512, 256, QA_SMB>>>(hn, ne1, ne2, Wq, bq, Wk, bk, Wv, bv, taw, tab);
  k_bmma2<<<dim3(4, 384, 2), 256, SMB>>>(0);     // (profiled slot) y1 & y2 from de
  k_wgen<<<dim3(390, 12), 256>>>(ne2, gwp, gw, 24960, 0);
  k_wgen<<<dim3(195, 12), 256>>>(ne2, uwp, uw, 12480, 1);
  k_wgen<<<dim3(2, 12), 256>>>(ne2, gbp, gb, 128, 2);
  k_wgen<<<dim3(1, 12), 256>>>(ne2, ubp, ub, 64, 3);
  k_combT<0><<<dim3(2, 4, 768), 256>>>(nullptr, nullptr, nullptr);   // yzf / rg
  k_bmma2<<<dim3(4, 384, 2), 256, SMB>>>(1);     // y1 & y2 from yz
  k_combT<1><<<dim3(1, 4, 768), 256>>>(outw, outb, out);             // hc + final proj
}